// round 2
// baseline (speedup 1.0000x reference)
#include <cuda_runtime.h>
#include <math.h>

// ---------------------------------------------------------------------------
// Problem constants
// ---------------------------------------------------------------------------
#define Bn    16
#define Cn    1024
#define Dn    512
#define Hn    8
#define HDn   64
#define En    8
#define Ktop  2
#define FFn   2048
#define Tn    (Bn*Cn)        /* 16384 tokens */
#define CAPn  5120
#define NSLOT (Tn*Ktop)      /* 32768 slots  */

// ---------------------------------------------------------------------------
// Scratch: single __device__ array, buffers aliased along the dataflow
// timeline to keep the static footprint small (~277 MB).
//
//   phase 1 (attention):  Q | K | V | ATT           (4 * NPROJ)
//   phase 2 (post-attn):  PRJ aliases Q, SRC aliases K
//   phase 3 (MoE):        DISP overlays V+ATT (+beyond), then H1 (one
//                         expert's hidden, reused for all 8), then Y.
// Safe because: V/ATT are dead before scatter writes DISP; DISP rows beyond
// each expert's count are never gathered (reference drops them too).
// ---------------------------------------------------------------------------
static constexpr size_t NPROJ    = (size_t)Tn * Dn;              // 8,388,608
static constexpr size_t OFF_Q    = 0;
static constexpr size_t OFF_K    = 1 * NPROJ;
static constexpr size_t OFF_V    = 2 * NPROJ;
static constexpr size_t OFF_ATTN = 3 * NPROJ;
static constexpr size_t OFF_PRJ  = OFF_Q;                        // alias
static constexpr size_t OFF_SRC  = OFF_K;                        // alias
static constexpr size_t OFF_DISP = OFF_V;                        // overlay
static constexpr size_t NDISP    = (size_t)En * CAPn * Dn;       // 20,971,520
static constexpr size_t OFF_H    = OFF_DISP + NDISP;
static constexpr size_t NH1      = (size_t)CAPn * FFn;           // 10,485,760
static constexpr size_t OFF_Y    = OFF_H + NH1;
static constexpr size_t OFF_TOPW = OFF_Y + NDISP;
static constexpr size_t SCRATCH_FLOATS = OFF_TOPW + NSLOT;       // ~69.2M

__device__ float g_scratch[SCRATCH_FLOATS];
__device__ int   g_iscratch[2 * NSLOT + 8];   // topi | slotpos | expert_count

// ---------------------------------------------------------------------------
// GELU (tanh approximation -- matches jax.nn.gelu default approximate=True)
// ---------------------------------------------------------------------------
static __device__ __forceinline__ float gelu_fn(float x) {
    float x3 = x * x * x;
    float u  = 0.7978845608028654f * (x + 0.044715f * x3);
    return 0.5f * x * (1.0f + tanhf(u));
}

// ---------------------------------------------------------------------------
// Tiled fp32 GEMM:  C[M,N] = A[M,K] @ B[K,N] + bias  (optional GELU)
// 64x64 tile, BK=16, 256 threads, 4x4 per-thread microtile.
// M, N multiples of 64; K multiple of 16 (true for all call sites).
// mcount (optional, device ptr): effective row count -> tile early-exit.
// ---------------------------------------------------------------------------
template <bool GELU>
__global__ __launch_bounds__(256) void gemm_bias_kernel(
    const float* __restrict__ A, int lda,
    const float* __restrict__ Bm, int ldb,
    const float* __restrict__ bias,
    float* __restrict__ C, int ldc,
    int Kd, const int* __restrict__ mcount)
{
    if (mcount && (int)(blockIdx.y * 64) >= *mcount) return;

    __shared__ float As[16][64];
    __shared__ float Bs[16][64];

    const int tid = threadIdx.x;
    const int tx  = tid & 15;      // column group (4 cols)
    const int ty  = tid >> 4;      // row group    (4 rows)

    const float* Ab = A + (size_t)blockIdx.y * 64 * lda;
    const float* Bb = Bm + blockIdx.x * 64;

    const int arow = tid >> 2;          // 0..63
    const int acol = (tid & 3) << 2;    // 0,4,8,12
    const int bkk  = tid >> 4;          // 0..15
    const int bc4  = (tid & 15) << 2;   // 0..60

    float acc[4][4] = {};

    for (int k0 = 0; k0 < Kd; k0 += 16) {
        float4 av = *(const float4*)(Ab + (size_t)arow * lda + (k0 + acol));
        float4 bv = *(const float4*)(Bb + (size_t)(k0 + bkk) * ldb + bc4);
        As[acol + 0][arow] = av.x;
        As[acol + 1][arow] = av.y;
        As[acol + 2][arow] = av.z;
        As[acol + 3][arow] = av.w;
        *(float4*)&Bs[bkk][bc4] = bv;
        __syncthreads();

        #pragma unroll
        for (int kk = 0; kk < 16; kk++) {
            float4 a = *(const float4*)&As[kk][ty << 2];
            float4 b = *(const float4*)&Bs[kk][tx << 2];
            acc[0][0] += a.x * b.x; acc[0][1] += a.x * b.y; acc[0][2] += a.x * b.z; acc[0][3] += a.x * b.w;
            acc[1][0] += a.y * b.x; acc[1][1] += a.y * b.y; acc[1][2] += a.y * b.z; acc[1][3] += a.y * b.w;
            acc[2][0] += a.z * b.x; acc[2][1] += a.z * b.y; acc[2][2] += a.z * b.z; acc[2][3] += a.z * b.w;
            acc[3][0] += a.w * b.x; acc[3][1] += a.w * b.y; acc[3][2] += a.w * b.z; acc[3][3] += a.w * b.w;
        }
        __syncthreads();
    }

    const int cb = blockIdx.x * 64 + (tx << 2);
    float4 b4 = *(const float4*)(bias + cb);
    float bb[4] = {b4.x, b4.y, b4.z, b4.w};

    #pragma unroll
    for (int i = 0; i < 4; i++) {
        size_t r = (size_t)blockIdx.y * 64 + (ty << 2) + i;
        float4 o;
        o.x = acc[i][0] + bb[0];
        o.y = acc[i][1] + bb[1];
        o.z = acc[i][2] + bb[2];
        o.w = acc[i][3] + bb[3];
        if (GELU) {
            o.x = gelu_fn(o.x); o.y = gelu_fn(o.y);
            o.z = gelu_fn(o.z); o.w = gelu_fn(o.w);
        }
        *(float4*)(C + r * ldc + cb) = o;
    }
}

// ---------------------------------------------------------------------------
// Flash-style attention.  grid = (C/64 q-tiles, B*H).  block = 64 threads.
// Each thread owns one query row (q in regs, 64 regs) + online softmax.
// Layout: Q/K/V/O are [T, D] with head h at columns [h*64, h*64+64).
// ---------------------------------------------------------------------------
__global__ __launch_bounds__(64) void attn_kernel(
    const float* __restrict__ Q, const float* __restrict__ Kb,
    const float* __restrict__ V, const int* __restrict__ mask,
    float* __restrict__ O)
{
    __shared__ float sK[64][68];   // pad 68: float4-aligned rows, low conflicts
    __shared__ float sV[64][68];
    __shared__ int   sM[64];

    const int bh = blockIdx.y;
    const int b  = bh >> 3, h = bh & 7;
    const int q0 = blockIdx.x << 6;
    const int t  = threadIdx.x;
    const size_t rowbase = (size_t)b * Cn;

    const float* Qb = Q + (rowbase + q0) * Dn + h * HDn;
    // stage q tile through sK (coalesced), copy to regs
    #pragma unroll
    for (int i = 0; i < 16; i++) {
        int idx = t + i * 64;
        int r = idx >> 4, c4 = (idx & 15) << 2;
        *(float4*)&sK[r][c4] = *(const float4*)(Qb + (size_t)r * Dn + c4);
    }
    __syncthreads();
    float qr[64];
    #pragma unroll
    for (int d = 0; d < 64; d++) qr[d] = sK[t][d] * 0.125f;  // 1/sqrt(64)

    float o[64];
    #pragma unroll
    for (int d = 0; d < 64; d++) o[d] = 0.0f;
    float mrun = -3.0e38f, lrun = 0.0f;

    const float* KB = Kb + rowbase * Dn + h * HDn;
    const float* VB = V  + rowbase * Dn + h * HDn;
    const int*   MB = mask + b * Cn;

    for (int k0 = 0; k0 < Cn; k0 += 64) {
        __syncthreads();
        #pragma unroll
        for (int i = 0; i < 16; i++) {
            int idx = t + i * 64;
            int r = idx >> 4, c4 = (idx & 15) << 2;
            *(float4*)&sK[r][c4] = *(const float4*)(KB + (size_t)(k0 + r) * Dn + c4);
            *(float4*)&sV[r][c4] = *(const float4*)(VB + (size_t)(k0 + r) * Dn + c4);
        }
        sM[t] = MB[k0 + t];
        __syncthreads();

        for (int kk = 0; kk < 64; kk++) {
            float s = 0.0f;
            #pragma unroll
            for (int d = 0; d < 64; d++) s += qr[d] * sK[kk][d];
            if (sM[kk] == 0) s = -1e10f;
            float mnew = fmaxf(mrun, s);
            float corr = __expf(mrun - mnew);
            float p    = __expf(s - mnew);
            lrun = lrun * corr + p;
            #pragma unroll
            for (int d = 0; d < 64; d++) o[d] = o[d] * corr + p * sV[kk][d];
            mrun = mnew;
        }
    }

    float inv = 1.0f / lrun;
    __syncthreads();
    #pragma unroll
    for (int d = 0; d < 64; d++) sK[t][d] = o[d] * inv;
    __syncthreads();
    float* Ob = O + (rowbase + q0) * Dn + h * HDn;
    #pragma unroll
    for (int i = 0; i < 16; i++) {
        int idx = t + i * 64;
        int r = idx >> 4, c4 = (idx & 15) << 2;
        *(float4*)(Ob + (size_t)r * Dn + c4) = *(float4*)&sK[r][c4];
    }
}

// ---------------------------------------------------------------------------
// Residual add + LayerNorm.  One warp per token row (512 elems, 16/lane).
// ---------------------------------------------------------------------------
__global__ __launch_bounds__(256) void add_ln_kernel(
    const float* __restrict__ A, const float* __restrict__ R,
    const float* __restrict__ gam, const float* __restrict__ bet,
    float* __restrict__ out)
{
    int w    = (blockIdx.x * 256 + threadIdx.x) >> 5;
    int lane = threadIdx.x & 31;
    const float4* a4 = (const float4*)(A + (size_t)w * Dn);
    const float4* r4 = (const float4*)(R + (size_t)w * Dn);
    float4 v[4];
    float s = 0.0f, s2 = 0.0f;
    #pragma unroll
    for (int i = 0; i < 4; i++) {
        float4 xa = a4[lane + i * 32], xr = r4[lane + i * 32];
        v[i].x = xa.x + xr.x; v[i].y = xa.y + xr.y;
        v[i].z = xa.z + xr.z; v[i].w = xa.w + xr.w;
        s  += v[i].x + v[i].y + v[i].z + v[i].w;
        s2 += v[i].x * v[i].x + v[i].y * v[i].y + v[i].z * v[i].z + v[i].w * v[i].w;
    }
    #pragma unroll
    for (int off = 16; off; off >>= 1) {
        s  += __shfl_xor_sync(0xffffffffu, s,  off);
        s2 += __shfl_xor_sync(0xffffffffu, s2, off);
    }
    float mean = s * (1.0f / Dn);
    float var  = s2 * (1.0f / Dn) - mean * mean;
    float inv  = rsqrtf(var + 1e-5f);
    const float4* g4 = (const float4*)gam;
    const float4* b4 = (const float4*)bet;
    float4* o4 = (float4*)(out + (size_t)w * Dn);
    #pragma unroll
    for (int i = 0; i < 4; i++) {
        float4 g = g4[lane + i * 32], be = b4[lane + i * 32];
        float4 r;
        r.x = (v[i].x - mean) * inv * g.x + be.x;
        r.y = (v[i].y - mean) * inv * g.y + be.y;
        r.z = (v[i].z - mean) * inv * g.z + be.z;
        r.w = (v[i].w - mean) * inv * g.w + be.w;
        o4[lane + i * 32] = r;
    }
}

// ---------------------------------------------------------------------------
// Router: logits = src @ rw[512,8]; softmax; top-2 (lower index wins ties,
// matching jax.lax.top_k); renormalize top-2 weights.  One warp per token.
// ---------------------------------------------------------------------------
__global__ __launch_bounds__(256) void router_kernel(
    const float* __restrict__ src, const float* __restrict__ rw,
    int* __restrict__ topi, float* __restrict__ topw)
{
    int w    = (blockIdx.x * 256 + threadIdx.x) >> 5;
    int lane = threadIdx.x & 31;
    const float* xr = src + (size_t)w * Dn;
    float acc[8] = {0, 0, 0, 0, 0, 0, 0, 0};
    for (int d = lane; d < Dn; d += 32) {
        float xv = xr[d];
        const float4* r4 = (const float4*)(rw + d * 8);
        float4 r0 = r4[0], r1 = r4[1];
        acc[0] += xv * r0.x; acc[1] += xv * r0.y; acc[2] += xv * r0.z; acc[3] += xv * r0.w;
        acc[4] += xv * r1.x; acc[5] += xv * r1.y; acc[6] += xv * r1.z; acc[7] += xv * r1.w;
    }
    #pragma unroll
    for (int e = 0; e < 8; e++)
        #pragma unroll
        for (int off = 16; off; off >>= 1)
            acc[e] += __shfl_xor_sync(0xffffffffu, acc[e], off);

    if (lane == 0) {
        float mx = acc[0];
        #pragma unroll
        for (int e = 1; e < 8; e++) mx = fmaxf(mx, acc[e]);
        float pe[8], sum = 0.0f;
        #pragma unroll
        for (int e = 0; e < 8; e++) { pe[e] = __expf(acc[e] - mx); sum += pe[e]; }
        float isum = 1.0f / sum;
        #pragma unroll
        for (int e = 0; e < 8; e++) pe[e] *= isum;
        int i1 = 0; float v1 = pe[0];
        #pragma unroll
        for (int e = 1; e < 8; e++) if (pe[e] > v1) { v1 = pe[e]; i1 = e; }
        int i2 = -1; float v2 = -1.0f;
        #pragma unroll
        for (int e = 0; e < 8; e++) if (e != i1 && pe[e] > v2) { v2 = pe[e]; i2 = e; }
        float wn = 1.0f / (v1 + v2);
        topi[2 * w]     = i1;  topi[2 * w + 1] = i2;
        topw[2 * w]     = v1 * wn;  topw[2 * w + 1] = v2 * wn;
    }
}

// ---------------------------------------------------------------------------
// Deterministic capacity scan.  Single block, 1024 threads, 32 slots each.
// Reproduces JAX cumsum-order ranks exactly (atomics would not).
// ---------------------------------------------------------------------------
__global__ __launch_bounds__(1024) void scan_kernel(
    const int* __restrict__ topi, int* __restrict__ slotpos,
    int* __restrict__ ecnt)
{
    __shared__ int wtot[32][8];
    __shared__ int wbase[32][8];
    int tid = threadIdx.x, lane = tid & 31, wid = tid >> 5;
    int base = tid * 32;

    int eid[32];
    #pragma unroll
    for (int i = 0; i < 32; i++) eid[i] = topi[base + i];

    int c[8];
    #pragma unroll
    for (int e = 0; e < 8; e++) {
        int ce = 0;
        #pragma unroll
        for (int i = 0; i < 32; i++) ce += (eid[i] == e);
        c[e] = ce;
    }

    int inc[8], excl[8];
    #pragma unroll
    for (int e = 0; e < 8; e++) {
        int v = c[e];
        for (int off = 1; off < 32; off <<= 1) {
            int n = __shfl_up_sync(0xffffffffu, v, off);
            if (lane >= off) v += n;
        }
        inc[e] = v; excl[e] = v - c[e];
    }
    if (lane == 31) {
        #pragma unroll
        for (int e = 0; e < 8; e++) wtot[wid][e] = inc[e];
    }
    __syncthreads();
    if (wid == 0) {
        #pragma unroll
        for (int e = 0; e < 8; e++) {
            int t = wtot[lane][e];
            int v = t;
            for (int off = 1; off < 32; off <<= 1) {
                int n = __shfl_up_sync(0xffffffffu, v, off);
                if (lane >= off) v += n;
            }
            wbase[lane][e] = v - t;
            if (lane == 31) ecnt[e] = min(v, CAPn);
        }
    }
    __syncthreads();

    int run[8];
    #pragma unroll
    for (int e = 0; e < 8; e++) run[e] = wbase[wid][e] + excl[e];

    #pragma unroll
    for (int i = 0; i < 32; i++) {
        int e = eid[i];
        int p = 0;
        #pragma unroll
        for (int ee = 0; ee < 8; ee++)
            if (e == ee) { p = run[ee]; run[ee] = p + 1; }
        slotpos[base + i] = (p < CAPn) ? p : -1;
    }
}

// ---------------------------------------------------------------------------
// Scatter kept slots into disp[E, CAP, D].  One 64-thread block per slot.
// ---------------------------------------------------------------------------
__global__ __launch_bounds__(64) void scatter_kernel(
    const float* __restrict__ src, const int* __restrict__ topi,
    const int* __restrict__ slotpos, float* __restrict__ disp)
{
    int s = blockIdx.x;
    int p = slotpos[s];
    if (p < 0) return;
    int e   = topi[s];
    int tok = s >> 1;
    const float4* in4  = (const float4*)(src + (size_t)tok * Dn);
    float4*       out4 = (float4*)(disp + ((size_t)e * CAPn + p) * Dn);
    int t = threadIdx.x;
    out4[t]      = in4[t];
    out4[t + 64] = in4[t + 64];
}

// ---------------------------------------------------------------------------
// Gather expert outputs, combine with weights, residual + LayerNorm2.
// One warp per token.
// ---------------------------------------------------------------------------
__global__ __launch_bounds__(256) void combine_ln_kernel(
    const float* __restrict__ src, const float* __restrict__ y,
    const int* __restrict__ topi, const float* __restrict__ topw,
    const int* __restrict__ slotpos,
    const float* __restrict__ gam, const float* __restrict__ bet,
    float* __restrict__ out)
{
    int w    = (blockIdx.x * 256 + threadIdx.x) >> 5;
    int lane = threadIdx.x & 31;
    const float4* s4 = (const float4*)(src + (size_t)w * Dn);
    float4 v[4];
    #pragma unroll
    for (int i = 0; i < 4; i++) v[i] = s4[lane + i * 32];

    #pragma unroll
    for (int kk = 0; kk < 2; kk++) {
        int slot = 2 * w + kk;
        int p = slotpos[slot];
        if (p >= 0) {
            int e = topi[slot];
            float ww = topw[slot];
            const float4* y4 = (const float4*)(y + ((size_t)e * CAPn + p) * Dn);
            #pragma unroll
            for (int i = 0; i < 4; i++) {
                float4 yy = y4[lane + i * 32];
                v[i].x += ww * yy.x; v[i].y += ww * yy.y;
                v[i].z += ww * yy.z; v[i].w += ww * yy.w;
            }
        }
    }

    float s = 0.0f, s2 = 0.0f;
    #pragma unroll
    for (int i = 0; i < 4; i++) {
        s  += v[i].x + v[i].y + v[i].z + v[i].w;
        s2 += v[i].x * v[i].x + v[i].y * v[i].y + v[i].z * v[i].z + v[i].w * v[i].w;
    }
    #pragma unroll
    for (int off = 16; off; off >>= 1) {
        s  += __shfl_xor_sync(0xffffffffu, s,  off);
        s2 += __shfl_xor_sync(0xffffffffu, s2, off);
    }
    float mean = s * (1.0f / Dn);
    float var  = s2 * (1.0f / Dn) - mean * mean;
    float inv  = rsqrtf(var + 1e-5f);
    const float4* g4 = (const float4*)gam;
    const float4* b4 = (const float4*)bet;
    float4* o4 = (float4*)(out + (size_t)w * Dn);
    #pragma unroll
    for (int i = 0; i < 4; i++) {
        float4 g = g4[lane + i * 32], be = b4[lane + i * 32];
        float4 r;
        r.x = (v[i].x - mean) * inv * g.x + be.x;
        r.y = (v[i].y - mean) * inv * g.y + be.y;
        r.z = (v[i].z - mean) * inv * g.z + be.z;
        r.w = (v[i].w - mean) * inv * g.w + be.w;
        o4[lane + i * 32] = r;
    }
}

// ---------------------------------------------------------------------------
// Launch sequence (graph-capturable: kernel launches only)
// ---------------------------------------------------------------------------
extern "C" void kernel_launch(void* const* d_in, const int* in_sizes, int n_in,
                              void* d_out, int out_size)
{
    const float* x    = (const float*)d_in[0];
    const int*   msk  = (const int*)  d_in[1];
    const float* wq   = (const float*)d_in[2];
    const float* bq   = (const float*)d_in[3];
    const float* wk   = (const float*)d_in[4];
    const float* bk   = (const float*)d_in[5];
    const float* wv   = (const float*)d_in[6];
    const float* bv   = (const float*)d_in[7];
    const float* wo   = (const float*)d_in[8];
    const float* bo   = (const float*)d_in[9];
    const float* ln1g = (const float*)d_in[10];
    const float* ln1b = (const float*)d_in[11];
    const float* ln2g = (const float*)d_in[12];
    const float* ln2b = (const float*)d_in[13];
    const float* rw   = (const float*)d_in[14];
    const float* w1   = (const float*)d_in[15];
    const float* b1   = (const float*)d_in[16];
    const float* w2   = (const float*)d_in[17];
    const float* b2   = (const float*)d_in[18];
    float* out = (float*)d_out;

    float* S = nullptr;
    int*   I = nullptr;
    cudaGetSymbolAddress((void**)&S, g_scratch);
    cudaGetSymbolAddress((void**)&I, g_iscratch);

    float* Qb   = S + OFF_Q;
    float* Kbuf = S + OFF_K;
    float* Vb   = S + OFF_V;
    float* ATT  = S + OFF_ATTN;
    float* PRJ  = S + OFF_PRJ;    // aliases Q (dead after attention)
    float* SRC  = S + OFF_SRC;    // aliases K (dead after attention)
    float* DISP = S + OFF_DISP;   // overlays V/ATT (dead after O-proj)
    float* Hb   = S + OFF_H;      // one expert's hidden, reused 8x
    float* Yb   = S + OFF_Y;
    float* TW   = S + OFF_TOPW;
    int* topi    = I;
    int* slotpos = I + NSLOT;
    int* ecnt    = I + 2 * NSLOT;

    dim3 blk(256);
    dim3 gproj(Dn / 64, Tn / 64);   // (8, 256)

    // --- attention block ---
    gemm_bias_kernel<false><<<gproj, blk>>>(x, Dn, wq, Dn, bq, Qb,   Dn, Dn, nullptr);
    gemm_bias_kernel<false><<<gproj, blk>>>(x, Dn, wk, Dn, bk, Kbuf, Dn, Dn, nullptr);
    gemm_bias_kernel<false><<<gproj, blk>>>(x, Dn, wv, Dn, bv, Vb,   Dn, Dn, nullptr);
    attn_kernel<<<dim3(Cn / 64, Bn * Hn), 64>>>(Qb, Kbuf, Vb, msk, ATT);
    gemm_bias_kernel<false><<<gproj, blk>>>(ATT, Dn, wo, Dn, bo, PRJ, Dn, Dn, nullptr);
    add_ln_kernel<<<Tn / 8, 256>>>(x, PRJ, ln1g, ln1b, SRC);

    // --- MoE block ---
    router_kernel<<<Tn / 8, 256>>>(SRC, rw, topi, TW);
    scan_kernel<<<1, 1024>>>(topi, slotpos, ecnt);
    scatter_kernel<<<NSLOT, 64>>>(SRC, topi, slotpos, DISP);

    // per-expert FFN, single shared hidden buffer (stream-ordered => safe)
    for (int e = 0; e < En; e++) {
        gemm_bias_kernel<true><<<dim3(FFn / 64, CAPn / 64), blk>>>(
            DISP + (size_t)e * CAPn * Dn, Dn,
            w1 + (size_t)e * Dn * FFn, FFn,
            b1 + (size_t)e * FFn,
            Hb, FFn,
            Dn, ecnt + e);
        gemm_bias_kernel<false><<<dim3(Dn / 64, CAPn / 64), blk>>>(
            Hb, FFn,
            w2 + (size_t)e * FFn * Dn, Dn,
            b2 + (size_t)e * Dn,
            Yb + (size_t)e * CAPn * Dn, Dn,
            FFn, ecnt + e);
    }

    combine_ln_kernel<<<Tn / 8, 256>>>(SRC, Yb, topi, TW, slotpos,
                                       ln2g, ln2b, out);
}

// round 4
// speedup vs baseline: 1.6871x; 1.6871x over previous
#include <cuda_runtime.h>
#include <math.h>
#include <stdint.h>

// ---------------------------------------------------------------------------
// Problem constants
// ---------------------------------------------------------------------------
#define Bn    16
#define Cn    1024
#define Dn    512
#define Hn    8
#define HDn   64
#define En    8
#define Ktop  2
#define FFn   2048
#define Tn    (Bn*Cn)        /* 16384 tokens */
#define CAPn  5120
#define NSLOT (Tn*Ktop)      /* 32768 slots  */

// ---------------------------------------------------------------------------
// Scratch: single __device__ array, buffers aliased along the dataflow
// timeline (~277 MB).
// ---------------------------------------------------------------------------
static constexpr size_t NPROJ    = (size_t)Tn * Dn;              // 8,388,608
static constexpr size_t OFF_Q    = 0;
static constexpr size_t OFF_K    = 1 * NPROJ;
static constexpr size_t OFF_V    = 2 * NPROJ;
static constexpr size_t OFF_ATTN = 3 * NPROJ;
static constexpr size_t OFF_PRJ  = OFF_Q;                        // alias
static constexpr size_t OFF_SRC  = OFF_K;                        // alias
static constexpr size_t OFF_DISP = OFF_V;                        // overlay
static constexpr size_t NDISP    = (size_t)En * CAPn * Dn;       // 20,971,520
static constexpr size_t OFF_H    = OFF_DISP + NDISP;
static constexpr size_t NH1      = (size_t)CAPn * FFn;           // 10,485,760
static constexpr size_t OFF_Y    = OFF_H + NH1;
static constexpr size_t OFF_TOPW = OFF_Y + NDISP;
static constexpr size_t SCRATCH_FLOATS = OFF_TOPW + NSLOT;

__device__ float g_scratch[SCRATCH_FLOATS];
__device__ int   g_iscratch[2 * NSLOT + 8];   // topi | slotpos | expert_count

// ---------------------------------------------------------------------------
// GELU (tanh approximation -- matches jax.nn.gelu default approximate=True)
// ---------------------------------------------------------------------------
static __device__ __forceinline__ float gelu_fn(float x) {
    float x3 = x * x * x;
    float u  = 0.7978845608028654f * (x + 0.044715f * x3);
    return 0.5f * x * (1.0f + tanhf(u));
}

static __device__ __forceinline__ uint32_t f2tf(float x) {
    uint32_t u;
    asm("cvt.rna.tf32.f32 %0, %1;" : "=r"(u) : "f"(x));
    return u;
}

// ---------------------------------------------------------------------------
// tf32 tensor-core GEMM:  C[M,N] = A[M,K] @ B[K,N] + bias (opt GELU)
// 128x128x32 tile, 256 threads (8 warps, 2x4), warp tile 64x32 via
// mma.sync.aligned.m16n8k8 tf32. Single smem stage + register-staged
// global prefetch. M,N multiples of 128; K multiple of 32.
// Smem stride 136 -> fragment LDS bank-conflict-free.
// mcount (device ptr, optional): row count -> tile early-exit.
// ---------------------------------------------------------------------------
#define BM 128
#define BN 128
#define BKt 32

template <bool GELU>
__global__ __launch_bounds__(256) void gemm_tf32_kernel(
    const float* __restrict__ A, int lda,
    const float* __restrict__ Bm, int ldb,
    const float* __restrict__ bias,
    float* __restrict__ C, int ldc,
    int Kd, const int* __restrict__ mcount)
{
    if (mcount && (int)(blockIdx.y * BM) >= *mcount) return;

    __shared__ uint32_t As[BKt][BM + 8];
    __shared__ uint32_t Bs[BKt][BN + 8];

    const int tid  = threadIdx.x;
    const int wid  = tid >> 5;
    const int lane = tid & 31;
    const int wm   = (wid & 1) * 64;     // warp m offset in tile
    const int wnn  = (wid >> 1) * 32;    // warp n offset in tile
    const int g    = lane >> 2;          // groupID 0..7
    const int tg   = lane & 3;           // thread-in-group 0..3

    // global staging assignments
    const int ar  = tid >> 1;            // A row 0..127
    const int ac0 = (tid & 1) * 16;      // A col base (16 floats per thread)
    const int br  = tid >> 3;            // B row (k) 0..31
    const int bc0 = (tid & 7) * 16;      // B col base (16 floats per thread)

    const float* Ab = A + (size_t)(blockIdx.y * BM + ar) * lda + ac0;
    const float* Bb = Bm + (size_t)br * ldb + blockIdx.x * BN + bc0;

    float4 av[4], bv[4];
    #pragma unroll
    for (int j = 0; j < 4; j++) av[j] = *(const float4*)(Ab + j * 4);
    #pragma unroll
    for (int j = 0; j < 4; j++) bv[j] = *(const float4*)(Bb + j * 4);

    float acc[4][4][4];
    #pragma unroll
    for (int i = 0; i < 4; i++)
        #pragma unroll
        for (int j = 0; j < 4; j++) {
            acc[i][j][0] = 0.f; acc[i][j][1] = 0.f;
            acc[i][j][2] = 0.f; acc[i][j][3] = 0.f;
        }

    const int ntile = Kd / BKt;

    // store tile 0
    #pragma unroll
    for (int j = 0; j < 4; j++) {
        As[ac0 + j * 4 + 0][ar] = f2tf(av[j].x);
        As[ac0 + j * 4 + 1][ar] = f2tf(av[j].y);
        As[ac0 + j * 4 + 2][ar] = f2tf(av[j].z);
        As[ac0 + j * 4 + 3][ar] = f2tf(av[j].w);
        uint4 u;
        u.x = f2tf(bv[j].x); u.y = f2tf(bv[j].y);
        u.z = f2tf(bv[j].z); u.w = f2tf(bv[j].w);
        *(uint4*)&Bs[br][bc0 + j * 4] = u;
    }
    __syncthreads();

    for (int kt = 0; kt < ntile; kt++) {
        if (kt + 1 < ntile) {
            const float* Anext = Ab + (kt + 1) * BKt;
            const float* Bnext = Bb + (size_t)(kt + 1) * BKt * ldb;
            #pragma unroll
            for (int j = 0; j < 4; j++) av[j] = *(const float4*)(Anext + j * 4);
            #pragma unroll
            for (int j = 0; j < 4; j++) bv[j] = *(const float4*)(Bnext + j * 4);
        }

        #pragma unroll
        for (int kc = 0; kc < 4; kc++) {
            const int k0 = kc * 8;
            uint32_t afr[4][4];
            #pragma unroll
            for (int i = 0; i < 4; i++) {
                int m = wm + i * 16 + g;
                afr[i][0] = As[k0 + tg][m];
                afr[i][1] = As[k0 + tg][m + 8];
                afr[i][2] = As[k0 + tg + 4][m];
                afr[i][3] = As[k0 + tg + 4][m + 8];
            }
            uint32_t bfr[4][2];
            #pragma unroll
            for (int j = 0; j < 4; j++) {
                int n = wnn + j * 8 + g;
                bfr[j][0] = Bs[k0 + tg][n];
                bfr[j][1] = Bs[k0 + tg + 4][n];
            }
            #pragma unroll
            for (int i = 0; i < 4; i++)
                #pragma unroll
                for (int j = 0; j < 4; j++) {
                    asm volatile(
                        "mma.sync.aligned.m16n8k8.row.col.f32.tf32.tf32.f32 "
                        "{%0,%1,%2,%3}, {%4,%5,%6,%7}, {%8,%9}, {%0,%1,%2,%3};"
                        : "+f"(acc[i][j][0]), "+f"(acc[i][j][1]),
                          "+f"(acc[i][j][2]), "+f"(acc[i][j][3])
                        : "r"(afr[i][0]), "r"(afr[i][1]),
                          "r"(afr[i][2]), "r"(afr[i][3]),
                          "r"(bfr[j][0]), "r"(bfr[j][1]));
                }
        }
        __syncthreads();

        if (kt + 1 < ntile) {
            #pragma unroll
            for (int j = 0; j < 4; j++) {
                As[ac0 + j * 4 + 0][ar] = f2tf(av[j].x);
                As[ac0 + j * 4 + 1][ar] = f2tf(av[j].y);
                As[ac0 + j * 4 + 2][ar] = f2tf(av[j].z);
                As[ac0 + j * 4 + 3][ar] = f2tf(av[j].w);
                uint4 u;
                u.x = f2tf(bv[j].x); u.y = f2tf(bv[j].y);
                u.z = f2tf(bv[j].z); u.w = f2tf(bv[j].w);
                *(uint4*)&Bs[br][bc0 + j * 4] = u;
            }
            __syncthreads();
        }
    }

    // epilogue: bias (+GELU), write float2 pairs
    #pragma unroll
    for (int j = 0; j < 4; j++) {
        const int col = blockIdx.x * BN + wnn + j * 8 + 2 * tg;
        const float2 bb = *(const float2*)(bias + col);
        #pragma unroll
        for (int i = 0; i < 4; i++) {
            const size_t row0 = (size_t)blockIdx.y * BM + wm + i * 16 + g;
            float2 v0, v1;
            v0.x = acc[i][j][0] + bb.x;
            v0.y = acc[i][j][1] + bb.y;
            v1.x = acc[i][j][2] + bb.x;
            v1.y = acc[i][j][3] + bb.y;
            if (GELU) {
                v0.x = gelu_fn(v0.x); v0.y = gelu_fn(v0.y);
                v1.x = gelu_fn(v1.x); v1.y = gelu_fn(v1.y);
            }
            *(float2*)(C + row0 * ldc + col)       = v0;
            *(float2*)(C + (row0 + 8) * ldc + col) = v1;
        }
    }
}

// ---------------------------------------------------------------------------
// Flash-style attention (fp32, unchanged).  grid = (C/64, B*H), block = 64.
// ---------------------------------------------------------------------------
__global__ __launch_bounds__(64) void attn_kernel(
    const float* __restrict__ Q, const float* __restrict__ Kb,
    const float* __restrict__ V, const int* __restrict__ mask,
    float* __restrict__ O)
{
    __shared__ float sK[64][68];
    __shared__ float sV[64][68];
    __shared__ int   sM[64];

    const int bh = blockIdx.y;
    const int b  = bh >> 3, h = bh & 7;
    const int q0 = blockIdx.x << 6;
    const int t  = threadIdx.x;
    const size_t rowbase = (size_t)b * Cn;

    const float* Qb = Q + (rowbase + q0) * Dn + h * HDn;
    #pragma unroll
    for (int i = 0; i < 16; i++) {
        int idx = t + i * 64;
        int r = idx >> 4, c4 = (idx & 15) << 2;
        *(float4*)&sK[r][c4] = *(const float4*)(Qb + (size_t)r * Dn + c4);
    }
    __syncthreads();
    float qr[64];
    #pragma unroll
    for (int d = 0; d < 64; d++) qr[d] = sK[t][d] * 0.125f;

    float o[64];
    #pragma unroll
    for (int d = 0; d < 64; d++) o[d] = 0.0f;
    float mrun = -3.0e38f, lrun = 0.0f;

    const float* KB = Kb + rowbase * Dn + h * HDn;
    const float* VB = V  + rowbase * Dn + h * HDn;
    const int*   MB = mask + b * Cn;

    for (int k0 = 0; k0 < Cn; k0 += 64) {
        __syncthreads();
        #pragma unroll
        for (int i = 0; i < 16; i++) {
            int idx = t + i * 64;
            int r = idx >> 4, c4 = (idx & 15) << 2;
            *(float4*)&sK[r][c4] = *(const float4*)(KB + (size_t)(k0 + r) * Dn + c4);
            *(float4*)&sV[r][c4] = *(const float4*)(VB + (size_t)(k0 + r) * Dn + c4);
        }
        sM[t] = MB[k0 + t];
        __syncthreads();

        for (int kk = 0; kk < 64; kk++) {
            float s = 0.0f;
            #pragma unroll
            for (int d = 0; d < 64; d++) s += qr[d] * sK[kk][d];
            if (sM[kk] == 0) s = -1e10f;
            float mnew = fmaxf(mrun, s);
            float corr = __expf(mrun - mnew);
            float p    = __expf(s - mnew);
            lrun = lrun * corr + p;
            #pragma unroll
            for (int d = 0; d < 64; d++) o[d] = o[d] * corr + p * sV[kk][d];
            mrun = mnew;
        }
    }

    float inv = 1.0f / lrun;
    __syncthreads();
    #pragma unroll
    for (int d = 0; d < 64; d++) sK[t][d] = o[d] * inv;
    __syncthreads();
    float* Ob = O + (rowbase + q0) * Dn + h * HDn;
    #pragma unroll
    for (int i = 0; i < 16; i++) {
        int idx = t + i * 64;
        int r = idx >> 4, c4 = (idx & 15) << 2;
        *(float4*)(Ob + (size_t)r * Dn + c4) = *(float4*)&sK[r][c4];
    }
}

// ---------------------------------------------------------------------------
// Residual add + LayerNorm.  One warp per token row.
// ---------------------------------------------------------------------------
__global__ __launch_bounds__(256) void add_ln_kernel(
    const float* __restrict__ A, const float* __restrict__ R,
    const float* __restrict__ gam, const float* __restrict__ bet,
    float* __restrict__ out)
{
    int w    = (blockIdx.x * 256 + threadIdx.x) >> 5;
    int lane = threadIdx.x & 31;
    const float4* a4 = (const float4*)(A + (size_t)w * Dn);
    const float4* r4 = (const float4*)(R + (size_t)w * Dn);
    float4 v[4];
    float s = 0.0f, s2 = 0.0f;
    #pragma unroll
    for (int i = 0; i < 4; i++) {
        float4 xa = a4[lane + i * 32], xr = r4[lane + i * 32];
        v[i].x = xa.x + xr.x; v[i].y = xa.y + xr.y;
        v[i].z = xa.z + xr.z; v[i].w = xa.w + xr.w;
        s  += v[i].x + v[i].y + v[i].z + v[i].w;
        s2 += v[i].x * v[i].x + v[i].y * v[i].y + v[i].z * v[i].z + v[i].w * v[i].w;
    }
    #pragma unroll
    for (int off = 16; off; off >>= 1) {
        s  += __shfl_xor_sync(0xffffffffu, s,  off);
        s2 += __shfl_xor_sync(0xffffffffu, s2, off);
    }
    float mean = s * (1.0f / Dn);
    float var  = s2 * (1.0f / Dn) - mean * mean;
    float inv  = rsqrtf(var + 1e-5f);
    const float4* g4 = (const float4*)gam;
    const float4* b4 = (const float4*)bet;
    float4* o4 = (float4*)(out + (size_t)w * Dn);
    #pragma unroll
    for (int i = 0; i < 4; i++) {
        float4 g = g4[lane + i * 32], be = b4[lane + i * 32];
        float4 r;
        r.x = (v[i].x - mean) * inv * g.x + be.x;
        r.y = (v[i].y - mean) * inv * g.y + be.y;
        r.z = (v[i].z - mean) * inv * g.z + be.z;
        r.w = (v[i].w - mean) * inv * g.w + be.w;
        o4[lane + i * 32] = r;
    }
}

// ---------------------------------------------------------------------------
// Router (unchanged).
// ---------------------------------------------------------------------------
__global__ __launch_bounds__(256) void router_kernel(
    const float* __restrict__ src, const float* __restrict__ rw,
    int* __restrict__ topi, float* __restrict__ topw)
{
    int w    = (blockIdx.x * 256 + threadIdx.x) >> 5;
    int lane = threadIdx.x & 31;
    const float* xr = src + (size_t)w * Dn;
    float acc[8] = {0, 0, 0, 0, 0, 0, 0, 0};
    for (int d = lane; d < Dn; d += 32) {
        float xv = xr[d];
        const float4* r4 = (const float4*)(rw + d * 8);
        float4 r0 = r4[0], r1 = r4[1];
        acc[0] += xv * r0.x; acc[1] += xv * r0.y; acc[2] += xv * r0.z; acc[3] += xv * r0.w;
        acc[4] += xv * r1.x; acc[5] += xv * r1.y; acc[6] += xv * r1.z; acc[7] += xv * r1.w;
    }
    #pragma unroll
    for (int e = 0; e < 8; e++)
        #pragma unroll
        for (int off = 16; off; off >>= 1)
            acc[e] += __shfl_xor_sync(0xffffffffu, acc[e], off);

    if (lane == 0) {
        float mx = acc[0];
        #pragma unroll
        for (int e = 1; e < 8; e++) mx = fmaxf(mx, acc[e]);
        float pe[8], sum = 0.0f;
        #pragma unroll
        for (int e = 0; e < 8; e++) { pe[e] = __expf(acc[e] - mx); sum += pe[e]; }
        float isum = 1.0f / sum;
        #pragma unroll
        for (int e = 0; e < 8; e++) pe[e] *= isum;
        int i1 = 0; float v1 = pe[0];
        #pragma unroll
        for (int e = 1; e < 8; e++) if (pe[e] > v1) { v1 = pe[e]; i1 = e; }
        int i2 = -1; float v2 = -1.0f;
        #pragma unroll
        for (int e = 0; e < 8; e++) if (e != i1 && pe[e] > v2) { v2 = pe[e]; i2 = e; }
        float wn = 1.0f / (v1 + v2);
        topi[2 * w]     = i1;  topi[2 * w + 1] = i2;
        topw[2 * w]     = v1 * wn;  topw[2 * w + 1] = v2 * wn;
    }
}

// ---------------------------------------------------------------------------
// Deterministic capacity scan (unchanged).
// ---------------------------------------------------------------------------
__global__ __launch_bounds__(1024) void scan_kernel(
    const int* __restrict__ topi, int* __restrict__ slotpos,
    int* __restrict__ ecnt)
{
    __shared__ int wtot[32][8];
    __shared__ int wbase[32][8];
    int tid = threadIdx.x, lane = tid & 31, wid = tid >> 5;
    int base = tid * 32;

    int eid[32];
    #pragma unroll
    for (int i = 0; i < 32; i++) eid[i] = topi[base + i];

    int c[8];
    #pragma unroll
    for (int e = 0; e < 8; e++) {
        int ce = 0;
        #pragma unroll
        for (int i = 0; i < 32; i++) ce += (eid[i] == e);
        c[e] = ce;
    }

    int inc[8], excl[8];
    #pragma unroll
    for (int e = 0; e < 8; e++) {
        int v = c[e];
        for (int off = 1; off < 32; off <<= 1) {
            int n = __shfl_up_sync(0xffffffffu, v, off);
            if (lane >= off) v += n;
        }
        inc[e] = v; excl[e] = v - c[e];
    }
    if (lane == 31) {
        #pragma unroll
        for (int e = 0; e < 8; e++) wtot[wid][e] = inc[e];
    }
    __syncthreads();
    if (wid == 0) {
        #pragma unroll
        for (int e = 0; e < 8; e++) {
            int t = wtot[lane][e];
            int v = t;
            for (int off = 1; off < 32; off <<= 1) {
                int n = __shfl_up_sync(0xffffffffu, v, off);
                if (lane >= off) v += n;
            }
            wbase[lane][e] = v - t;
            if (lane == 31) ecnt[e] = min(v, CAPn);
        }
    }
    __syncthreads();

    int run[8];
    #pragma unroll
    for (int e = 0; e < 8; e++) run[e] = wbase[wid][e] + excl[e];

    #pragma unroll
    for (int i = 0; i < 32; i++) {
        int e = eid[i];
        int p = 0;
        #pragma unroll
        for (int ee = 0; ee < 8; ee++)
            if (e == ee) { p = run[ee]; run[ee] = p + 1; }
        slotpos[base + i] = (p < CAPn) ? p : -1;
    }
}

// ---------------------------------------------------------------------------
// Scatter kept slots into disp[E, CAP, D] (unchanged).
// ---------------------------------------------------------------------------
__global__ __launch_bounds__(64) void scatter_kernel(
    const float* __restrict__ src, const int* __restrict__ topi,
    const int* __restrict__ slotpos, float* __restrict__ disp)
{
    int s = blockIdx.x;
    int p = slotpos[s];
    if (p < 0) return;
    int e   = topi[s];
    int tok = s >> 1;
    const float4* in4  = (const float4*)(src + (size_t)tok * Dn);
    float4*       out4 = (float4*)(disp + ((size_t)e * CAPn + p) * Dn);
    int t = threadIdx.x;
    out4[t]      = in4[t];
    out4[t + 64] = in4[t + 64];
}

// ---------------------------------------------------------------------------
// Gather + combine + residual + LayerNorm2 (unchanged).
// ---------------------------------------------------------------------------
__global__ __launch_bounds__(256) void combine_ln_kernel(
    const float* __restrict__ src, const float* __restrict__ y,
    const int* __restrict__ topi, const float* __restrict__ topw,
    const int* __restrict__ slotpos,
    const float* __restrict__ gam, const float* __restrict__ bet,
    float* __restrict__ out)
{
    int w    = (blockIdx.x * 256 + threadIdx.x) >> 5;
    int lane = threadIdx.x & 31;
    const float4* s4 = (const float4*)(src + (size_t)w * Dn);
    float4 v[4];
    #pragma unroll
    for (int i = 0; i < 4; i++) v[i] = s4[lane + i * 32];

    #pragma unroll
    for (int kk = 0; kk < 2; kk++) {
        int slot = 2 * w + kk;
        int p = slotpos[slot];
        if (p >= 0) {
            int e = topi[slot];
            float ww = topw[slot];
            const float4* y4 = (const float4*)(y + ((size_t)e * CAPn + p) * Dn);
            #pragma unroll
            for (int i = 0; i < 4; i++) {
                float4 yy = y4[lane + i * 32];
                v[i].x += ww * yy.x; v[i].y += ww * yy.y;
                v[i].z += ww * yy.z; v[i].w += ww * yy.w;
            }
        }
    }

    float s = 0.0f, s2 = 0.0f;
    #pragma unroll
    for (int i = 0; i < 4; i++) {
        s  += v[i].x + v[i].y + v[i].z + v[i].w;
        s2 += v[i].x * v[i].x + v[i].y * v[i].y + v[i].z * v[i].z + v[i].w * v[i].w;
    }
    #pragma unroll
    for (int off = 16; off; off >>= 1) {
        s  += __shfl_xor_sync(0xffffffffu, s,  off);
        s2 += __shfl_xor_sync(0xffffffffu, s2, off);
    }
    float mean = s * (1.0f / Dn);
    float var  = s2 * (1.0f / Dn) - mean * mean;
    float inv  = rsqrtf(var + 1e-5f);
    const float4* g4 = (const float4*)gam;
    const float4* b4 = (const float4*)bet;
    float4* o4 = (float4*)(out + (size_t)w * Dn);
    #pragma unroll
    for (int i = 0; i < 4; i++) {
        float4 g = g4[lane + i * 32], be = b4[lane + i * 32];
        float4 r;
        r.x = (v[i].x - mean) * inv * g.x + be.x;
        r.y = (v[i].y - mean) * inv * g.y + be.y;
        r.z = (v[i].z - mean) * inv * g.z + be.z;
        r.w = (v[i].w - mean) * inv * g.w + be.w;
        o4[lane + i * 32] = r;
    }
}

// ---------------------------------------------------------------------------
// Launch sequence (graph-capturable: kernel launches only)
// ---------------------------------------------------------------------------
extern "C" void kernel_launch(void* const* d_in, const int* in_sizes, int n_in,
                              void* d_out, int out_size)
{
    const float* x    = (const float*)d_in[0];
    const int*   msk  = (const int*)  d_in[1];
    const float* wq   = (const float*)d_in[2];
    const float* bq   = (const float*)d_in[3];
    const float* wk   = (const float*)d_in[4];
    const float* bk   = (const float*)d_in[5];
    const float* wv   = (const float*)d_in[6];
    const float* bv   = (const float*)d_in[7];
    const float* wo   = (const float*)d_in[8];
    const float* bo   = (const float*)d_in[9];
    const float* ln1g = (const float*)d_in[10];
    const float* ln1b = (const float*)d_in[11];
    const float* ln2g = (const float*)d_in[12];
    const float* ln2b = (const float*)d_in[13];
    const float* rw   = (const float*)d_in[14];
    const float* w1   = (const float*)d_in[15];
    const float* b1   = (const float*)d_in[16];
    const float* w2   = (const float*)d_in[17];
    const float* b2   = (const float*)d_in[18];
    float* out = (float*)d_out;

    float* S = nullptr;
    int*   I = nullptr;
    cudaGetSymbolAddress((void**)&S, g_scratch);
    cudaGetSymbolAddress((void**)&I, g_iscratch);

    float* Qb   = S + OFF_Q;
    float* Kbuf = S + OFF_K;
    float* Vb   = S + OFF_V;
    float* ATT  = S + OFF_ATTN;
    float* PRJ  = S + OFF_PRJ;
    float* SRC  = S + OFF_SRC;
    float* DISP = S + OFF_DISP;
    float* Hb   = S + OFF_H;
    float* Yb   = S + OFF_Y;
    float* TW   = S + OFF_TOPW;
    int* topi    = I;
    int* slotpos = I + NSLOT;
    int* ecnt    = I + 2 * NSLOT;

    dim3 blk(256);
    dim3 gproj(Dn / BN, Tn / BM);     // (4, 128)

    // --- attention block ---
    gemm_tf32_kernel<false><<<gproj, blk>>>(x, Dn, wq, Dn, bq, Qb,   Dn, Dn, nullptr);
    gemm_tf32_kernel<false><<<gproj, blk>>>(x, Dn, wk, Dn, bk, Kbuf, Dn, Dn, nullptr);
    gemm_tf32_kernel<false><<<gproj, blk>>>(x, Dn, wv, Dn, bv, Vb,   Dn, Dn, nullptr);
    attn_kernel<<<dim3(Cn / 64, Bn * Hn), 64>>>(Qb, Kbuf, Vb, msk, ATT);
    gemm_tf32_kernel<false><<<gproj, blk>>>(ATT, Dn, wo, Dn, bo, PRJ, Dn, Dn, nullptr);
    add_ln_kernel<<<Tn / 8, 256>>>(x, PRJ, ln1g, ln1b, SRC);

    // --- MoE block ---
    router_kernel<<<Tn / 8, 256>>>(SRC, rw, topi, TW);
    scan_kernel<<<1, 1024>>>(topi, slotpos, ecnt);
    scatter_kernel<<<NSLOT, 64>>>(SRC, topi, slotpos, DISP);

    for (int e = 0; e < En; e++) {
        gemm_tf32_kernel<true><<<dim3(FFn / BN, CAPn / BM), blk>>>(
            DISP + (size_t)e * CAPn * Dn, Dn,
            w1 + (size_t)e * Dn * FFn, FFn,
            b1 + (size_t)e * FFn,
            Hb, FFn,
            Dn, ecnt + e);
        gemm_tf32_kernel<false><<<dim3(Dn / BN, CAPn / BM), blk>>>(
            Hb, FFn,
            w2 + (size_t)e * FFn * Dn, Dn,
            b2 + (size_t)e * Dn,
            Yb + (size_t)e * CAPn * Dn, Dn,
            FFn, ecnt + e);
    }

    combine_ln_kernel<<<Tn / 8, 256>>>(SRC, Yb, topi, TW, slotpos,
                                       ln2g, ln2b, out);
}

// round 5
// speedup vs baseline: 2.3932x; 1.4185x over previous
#include <cuda_runtime.h>
#include <math.h>
#include <stdint.h>

// ---------------------------------------------------------------------------
// Problem constants
// ---------------------------------------------------------------------------
#define Bn    16
#define Cn    1024
#define Dn    512
#define Hn    8
#define HDn   64
#define En    8
#define Ktop  2
#define FFn   2048
#define Tn    (Bn*Cn)        /* 16384 tokens */
#define CAPn  5120
#define NSLOT (Tn*Ktop)      /* 32768 slots  */

// ---------------------------------------------------------------------------
// Scratch
// ---------------------------------------------------------------------------
static constexpr size_t NPROJ    = (size_t)Tn * Dn;
static constexpr size_t OFF_Q    = 0;
static constexpr size_t OFF_K    = 1 * NPROJ;
static constexpr size_t OFF_V    = 2 * NPROJ;
static constexpr size_t OFF_ATTN = 3 * NPROJ;
static constexpr size_t OFF_PRJ  = OFF_Q;
static constexpr size_t OFF_SRC  = OFF_K;
static constexpr size_t OFF_DISP = OFF_V;
static constexpr size_t NDISP    = (size_t)En * CAPn * Dn;
static constexpr size_t OFF_H    = OFF_DISP + NDISP;
static constexpr size_t NH1      = (size_t)CAPn * FFn;
static constexpr size_t OFF_Y    = OFF_H + NH1;
static constexpr size_t OFF_TOPW = OFF_Y + NDISP;
static constexpr size_t SCRATCH_FLOATS = OFF_TOPW + NSLOT;

__device__ float g_scratch[SCRATCH_FLOATS];
__device__ int   g_iscratch[2 * NSLOT + 8];

// ---------------------------------------------------------------------------
static __device__ __forceinline__ float gelu_fn(float x) {
    float x3 = x * x * x;
    float u  = 0.7978845608028654f * (x + 0.044715f * x3);
    return 0.5f * x * (1.0f + tanhf(u));
}

static __device__ __forceinline__ uint32_t f2tf(float x) {
    uint32_t u;
    asm("cvt.rna.tf32.f32 %0, %1;" : "=r"(u) : "f"(x));
    return u;
}

#define MMA_TF32(acc, a, b0, b1)                                              \
    asm volatile(                                                             \
        "mma.sync.aligned.m16n8k8.row.col.f32.tf32.tf32.f32 "                 \
        "{%0,%1,%2,%3}, {%4,%5,%6,%7}, {%8,%9}, {%0,%1,%2,%3};"               \
        : "+f"(acc[0]), "+f"(acc[1]), "+f"(acc[2]), "+f"(acc[3])              \
        : "r"(a[0]), "r"(a[1]), "r"(a[2]), "r"(a[3]), "r"(b0), "r"(b1))

// ---------------------------------------------------------------------------
// tf32 tensor-core GEMM (verified in R4, unchanged)
// ---------------------------------------------------------------------------
#define BM 128
#define BN 128
#define BKt 32

template <bool GELU>
__global__ __launch_bounds__(256) void gemm_tf32_kernel(
    const float* __restrict__ A, int lda,
    const float* __restrict__ Bm, int ldb,
    const float* __restrict__ bias,
    float* __restrict__ C, int ldc,
    int Kd, const int* __restrict__ mcount)
{
    if (mcount && (int)(blockIdx.y * BM) >= *mcount) return;

    __shared__ uint32_t As[BKt][BM + 8];
    __shared__ uint32_t Bs[BKt][BN + 8];

    const int tid  = threadIdx.x;
    const int wid  = tid >> 5;
    const int lane = tid & 31;
    const int wm   = (wid & 1) * 64;
    const int wnn  = (wid >> 1) * 32;
    const int g    = lane >> 2;
    const int tg   = lane & 3;

    const int ar  = tid >> 1;
    const int ac0 = (tid & 1) * 16;
    const int br  = tid >> 3;
    const int bc0 = (tid & 7) * 16;

    const float* Ab = A + (size_t)(blockIdx.y * BM + ar) * lda + ac0;
    const float* Bb = Bm + (size_t)br * ldb + blockIdx.x * BN + bc0;

    float4 av[4], bv[4];
    #pragma unroll
    for (int j = 0; j < 4; j++) av[j] = *(const float4*)(Ab + j * 4);
    #pragma unroll
    for (int j = 0; j < 4; j++) bv[j] = *(const float4*)(Bb + j * 4);

    float acc[4][4][4];
    #pragma unroll
    for (int i = 0; i < 4; i++)
        #pragma unroll
        for (int j = 0; j < 4; j++) {
            acc[i][j][0] = 0.f; acc[i][j][1] = 0.f;
            acc[i][j][2] = 0.f; acc[i][j][3] = 0.f;
        }

    const int ntile = Kd / BKt;

    #pragma unroll
    for (int j = 0; j < 4; j++) {
        As[ac0 + j * 4 + 0][ar] = f2tf(av[j].x);
        As[ac0 + j * 4 + 1][ar] = f2tf(av[j].y);
        As[ac0 + j * 4 + 2][ar] = f2tf(av[j].z);
        As[ac0 + j * 4 + 3][ar] = f2tf(av[j].w);
        uint4 u;
        u.x = f2tf(bv[j].x); u.y = f2tf(bv[j].y);
        u.z = f2tf(bv[j].z); u.w = f2tf(bv[j].w);
        *(uint4*)&Bs[br][bc0 + j * 4] = u;
    }
    __syncthreads();

    for (int kt = 0; kt < ntile; kt++) {
        if (kt + 1 < ntile) {
            const float* Anext = Ab + (kt + 1) * BKt;
            const float* Bnext = Bb + (size_t)(kt + 1) * BKt * ldb;
            #pragma unroll
            for (int j = 0; j < 4; j++) av[j] = *(const float4*)(Anext + j * 4);
            #pragma unroll
            for (int j = 0; j < 4; j++) bv[j] = *(const float4*)(Bnext + j * 4);
        }

        #pragma unroll
        for (int kc = 0; kc < 4; kc++) {
            const int k0 = kc * 8;
            uint32_t afr[4][4];
            #pragma unroll
            for (int i = 0; i < 4; i++) {
                int m = wm + i * 16 + g;
                afr[i][0] = As[k0 + tg][m];
                afr[i][1] = As[k0 + tg][m + 8];
                afr[i][2] = As[k0 + tg + 4][m];
                afr[i][3] = As[k0 + tg + 4][m + 8];
            }
            uint32_t bfr[4][2];
            #pragma unroll
            for (int j = 0; j < 4; j++) {
                int n = wnn + j * 8 + g;
                bfr[j][0] = Bs[k0 + tg][n];
                bfr[j][1] = Bs[k0 + tg + 4][n];
            }
            #pragma unroll
            for (int i = 0; i < 4; i++)
                #pragma unroll
                for (int j = 0; j < 4; j++)
                    MMA_TF32(acc[i][j], afr[i], bfr[j][0], bfr[j][1]);
        }
        __syncthreads();

        if (kt + 1 < ntile) {
            #pragma unroll
            for (int j = 0; j < 4; j++) {
                As[ac0 + j * 4 + 0][ar] = f2tf(av[j].x);
                As[ac0 + j * 4 + 1][ar] = f2tf(av[j].y);
                As[ac0 + j * 4 + 2][ar] = f2tf(av[j].z);
                As[ac0 + j * 4 + 3][ar] = f2tf(av[j].w);
                uint4 u;
                u.x = f2tf(bv[j].x); u.y = f2tf(bv[j].y);
                u.z = f2tf(bv[j].z); u.w = f2tf(bv[j].w);
                *(uint4*)&Bs[br][bc0 + j * 4] = u;
            }
            __syncthreads();
        }
    }

    #pragma unroll
    for (int j = 0; j < 4; j++) {
        const int col = blockIdx.x * BN + wnn + j * 8 + 2 * tg;
        const float2 bb = *(const float2*)(bias + col);
        #pragma unroll
        for (int i = 0; i < 4; i++) {
            const size_t row0 = (size_t)blockIdx.y * BM + wm + i * 16 + g;
            float2 v0, v1;
            v0.x = acc[i][j][0] + bb.x;
            v0.y = acc[i][j][1] + bb.y;
            v1.x = acc[i][j][2] + bb.x;
            v1.y = acc[i][j][3] + bb.y;
            if (GELU) {
                v0.x = gelu_fn(v0.x); v0.y = gelu_fn(v0.y);
                v1.x = gelu_fn(v1.x); v1.y = gelu_fn(v1.y);
            }
            *(float2*)(C + row0 * ldc + col)       = v0;
            *(float2*)(C + (row0 + 8) * ldc + col) = v1;
        }
    }
}

// ---------------------------------------------------------------------------
// Flash attention, tf32 tensor cores.
// grid = (Cn/64, B*H), block = 128 (4 warps). Warp w owns q rows 16w..16w+15.
// Q A-fragments register-resident (pre-scaled by 1/8). K tile 64x64 (pad 68),
// V tile 64x64 (pad 72); pads chosen for conflict-free B-fragment LDS.
// S = Q@K^T via MMA; online softmax on fragments (quad shuffles);
// P -> per-warp smem panel (pad 36) -> A-fragments -> P@V via MMA.
// ---------------------------------------------------------------------------
__global__ __launch_bounds__(128) void attn_mma_kernel(
    const float* __restrict__ Q, const float* __restrict__ Kb,
    const float* __restrict__ V, const int* __restrict__ mask,
    float* __restrict__ O)
{
    __shared__ uint32_t sK[64][68];      // K tile (tf32); Q staging at start
    __shared__ uint32_t sV[64][72];      // V tile (tf32)
    __shared__ uint32_t sP[4][16][36];   // per-warp P chunk (tf32)
    __shared__ int      sM[64];

    const int tid  = threadIdx.x;
    const int w    = tid >> 5;
    const int lane = tid & 31;
    const int g    = lane >> 2;
    const int tg   = lane & 3;

    const int bh = blockIdx.y;
    const int b  = bh >> 3, h = bh & 7;
    const int q0 = blockIdx.x << 6;
    const size_t rowbase = (size_t)b * Cn;

    const float* QB = Q  + (rowbase + q0) * Dn + h * HDn;
    const float* KB = Kb + rowbase * Dn + h * HDn;
    const float* VB = V  + rowbase * Dn + h * HDn;
    const int*   MB = mask + b * Cn;

    // ---- stage Q tile (scaled, tf32) into sK, extract A-fragments ----
    #pragma unroll
    for (int i = 0; i < 8; i++) {
        int slot = tid + i * 128;
        int r = slot >> 4, c4 = (slot & 15) << 2;
        float4 qv = *(const float4*)(QB + (size_t)r * Dn + c4);
        sK[r][c4 + 0] = f2tf(qv.x * 0.125f);
        sK[r][c4 + 1] = f2tf(qv.y * 0.125f);
        sK[r][c4 + 2] = f2tf(qv.z * 0.125f);
        sK[r][c4 + 3] = f2tf(qv.w * 0.125f);
    }
    __syncthreads();

    const int row0 = w * 16 + g;
    uint32_t qa[8][4];
    #pragma unroll
    for (int ks = 0; ks < 8; ks++) {
        qa[ks][0] = sK[row0][8 * ks + tg];
        qa[ks][1] = sK[row0 + 8][8 * ks + tg];
        qa[ks][2] = sK[row0][8 * ks + tg + 4];
        qa[ks][3] = sK[row0 + 8][8 * ks + tg + 4];
    }
    __syncthreads();

    float o[8][4];
    #pragma unroll
    for (int jn = 0; jn < 8; jn++) {
        o[jn][0] = 0.f; o[jn][1] = 0.f; o[jn][2] = 0.f; o[jn][3] = 0.f;
    }
    float mrun0 = -3.0e38f, mrun1 = -3.0e38f;
    float lrun0 = 0.f, lrun1 = 0.f;

    for (int kt = 0; kt < Cn / 64; kt++) {
        const int k0 = kt * 64;
        // ---- load K,V tiles (tf32) ----
        #pragma unroll
        for (int i = 0; i < 8; i++) {
            int slot = tid + i * 128;
            int r = slot >> 4, c4 = (slot & 15) << 2;
            float4 kv = *(const float4*)(KB + (size_t)(k0 + r) * Dn + c4);
            float4 vv = *(const float4*)(VB + (size_t)(k0 + r) * Dn + c4);
            sK[r][c4 + 0] = f2tf(kv.x); sK[r][c4 + 1] = f2tf(kv.y);
            sK[r][c4 + 2] = f2tf(kv.z); sK[r][c4 + 3] = f2tf(kv.w);
            sV[r][c4 + 0] = f2tf(vv.x); sV[r][c4 + 1] = f2tf(vv.y);
            sV[r][c4 + 2] = f2tf(vv.z); sV[r][c4 + 3] = f2tf(vv.w);
        }
        if (tid < 64) sM[tid] = MB[k0 + tid];
        __syncthreads();

        #pragma unroll
        for (int kc = 0; kc < 2; kc++) {
            // ---- S = Q @ K^T for 32-key chunk ----
            float sacc[4][4];
            #pragma unroll
            for (int j = 0; j < 4; j++) {
                sacc[j][0] = 0.f; sacc[j][1] = 0.f;
                sacc[j][2] = 0.f; sacc[j][3] = 0.f;
            }
            #pragma unroll
            for (int ks = 0; ks < 8; ks++) {
                #pragma unroll
                for (int j = 0; j < 4; j++) {
                    int n = kc * 32 + 8 * j + g;
                    uint32_t b0 = sK[n][8 * ks + tg];
                    uint32_t b1 = sK[n][8 * ks + tg + 4];
                    MMA_TF32(sacc[j], qa[ks], b0, b1);
                }
            }

            // ---- mask ----
            #pragma unroll
            for (int j = 0; j < 4; j++) {
                int c = kc * 32 + 8 * j + 2 * tg;
                if (sM[c] == 0)     { sacc[j][0] = -1e10f; sacc[j][2] = -1e10f; }
                if (sM[c + 1] == 0) { sacc[j][1] = -1e10f; sacc[j][3] = -1e10f; }
            }

            // ---- online softmax (rows g and g+8) ----
            float mx0 = -3.0e38f, mx1 = -3.0e38f;
            #pragma unroll
            for (int j = 0; j < 4; j++) {
                mx0 = fmaxf(mx0, fmaxf(sacc[j][0], sacc[j][1]));
                mx1 = fmaxf(mx1, fmaxf(sacc[j][2], sacc[j][3]));
            }
            mx0 = fmaxf(mx0, __shfl_xor_sync(0xffffffffu, mx0, 1));
            mx0 = fmaxf(mx0, __shfl_xor_sync(0xffffffffu, mx0, 2));
            mx1 = fmaxf(mx1, __shfl_xor_sync(0xffffffffu, mx1, 1));
            mx1 = fmaxf(mx1, __shfl_xor_sync(0xffffffffu, mx1, 2));

            float mnew0 = fmaxf(mrun0, mx0);
            float mnew1 = fmaxf(mrun1, mx1);
            float corr0 = __expf(mrun0 - mnew0);
            float corr1 = __expf(mrun1 - mnew1);
            mrun0 = mnew0; mrun1 = mnew1;

            float p[4][4];
            float ls0 = 0.f, ls1 = 0.f;
            #pragma unroll
            for (int j = 0; j < 4; j++) {
                p[j][0] = __expf(sacc[j][0] - mnew0);
                p[j][1] = __expf(sacc[j][1] - mnew0);
                p[j][2] = __expf(sacc[j][2] - mnew1);
                p[j][3] = __expf(sacc[j][3] - mnew1);
                ls0 += p[j][0] + p[j][1];
                ls1 += p[j][2] + p[j][3];
            }
            ls0 += __shfl_xor_sync(0xffffffffu, ls0, 1);
            ls0 += __shfl_xor_sync(0xffffffffu, ls0, 2);
            ls1 += __shfl_xor_sync(0xffffffffu, ls1, 1);
            ls1 += __shfl_xor_sync(0xffffffffu, ls1, 2);
            lrun0 = lrun0 * corr0 + ls0;
            lrun1 = lrun1 * corr1 + ls1;

            #pragma unroll
            for (int jn = 0; jn < 8; jn++) {
                o[jn][0] *= corr0; o[jn][1] *= corr0;
                o[jn][2] *= corr1; o[jn][3] *= corr1;
            }

            // ---- P -> smem panel (tf32) ----
            #pragma unroll
            for (int j = 0; j < 4; j++) {
                int c = 8 * j + 2 * tg;
                sP[w][g][c]         = f2tf(p[j][0]);
                sP[w][g][c + 1]     = f2tf(p[j][1]);
                sP[w][g + 8][c]     = f2tf(p[j][2]);
                sP[w][g + 8][c + 1] = f2tf(p[j][3]);
            }
            __syncwarp();

            uint32_t pa[4][4];
            #pragma unroll
            for (int ks = 0; ks < 4; ks++) {
                pa[ks][0] = sP[w][g][8 * ks + tg];
                pa[ks][1] = sP[w][g + 8][8 * ks + tg];
                pa[ks][2] = sP[w][g][8 * ks + tg + 4];
                pa[ks][3] = sP[w][g + 8][8 * ks + tg + 4];
            }
            __syncwarp();

            // ---- O += P @ V ----
            #pragma unroll
            for (int ks = 0; ks < 4; ks++) {
                int kr = kc * 32 + 8 * ks;
                #pragma unroll
                for (int jn = 0; jn < 8; jn++) {
                    uint32_t b0 = sV[kr + tg][8 * jn + g];
                    uint32_t b1 = sV[kr + tg + 4][8 * jn + g];
                    MMA_TF32(o[jn], pa[ks], b0, b1);
                }
            }
        }
        __syncthreads();
    }

    // ---- normalize + write ----
    const float inv0 = 1.0f / lrun0;
    const float inv1 = 1.0f / lrun1;
    const size_t grow = rowbase + q0 + row0;
    float* OB = O;
    #pragma unroll
    for (int jn = 0; jn < 8; jn++) {
        int col = h * HDn + 8 * jn + 2 * tg;
        float2 v0, v1;
        v0.x = o[jn][0] * inv0; v0.y = o[jn][1] * inv0;
        v1.x = o[jn][2] * inv1; v1.y = o[jn][3] * inv1;
        *(float2*)(OB + grow * Dn + col)       = v0;
        *(float2*)(OB + (grow + 8) * Dn + col) = v1;
    }
}

// ---------------------------------------------------------------------------
// Residual add + LayerNorm (unchanged).
// ---------------------------------------------------------------------------
__global__ __launch_bounds__(256) void add_ln_kernel(
    const float* __restrict__ A, const float* __restrict__ R,
    const float* __restrict__ gam, const float* __restrict__ bet,
    float* __restrict__ out)
{
    int w    = (blockIdx.x * 256 + threadIdx.x) >> 5;
    int lane = threadIdx.x & 31;
    const float4* a4 = (const float4*)(A + (size_t)w * Dn);
    const float4* r4 = (const float4*)(R + (size_t)w * Dn);
    float4 v[4];
    float s = 0.0f, s2 = 0.0f;
    #pragma unroll
    for (int i = 0; i < 4; i++) {
        float4 xa = a4[lane + i * 32], xr = r4[lane + i * 32];
        v[i].x = xa.x + xr.x; v[i].y = xa.y + xr.y;
        v[i].z = xa.z + xr.z; v[i].w = xa.w + xr.w;
        s  += v[i].x + v[i].y + v[i].z + v[i].w;
        s2 += v[i].x * v[i].x + v[i].y * v[i].y + v[i].z * v[i].z + v[i].w * v[i].w;
    }
    #pragma unroll
    for (int off = 16; off; off >>= 1) {
        s  += __shfl_xor_sync(0xffffffffu, s,  off);
        s2 += __shfl_xor_sync(0xffffffffu, s2, off);
    }
    float mean = s * (1.0f / Dn);
    float var  = s2 * (1.0f / Dn) - mean * mean;
    float inv  = rsqrtf(var + 1e-5f);
    const float4* g4 = (const float4*)gam;
    const float4* b4 = (const float4*)bet;
    float4* o4 = (float4*)(out + (size_t)w * Dn);
    #pragma unroll
    for (int i = 0; i < 4; i++) {
        float4 g = g4[lane + i * 32], be = b4[lane + i * 32];
        float4 r;
        r.x = (v[i].x - mean) * inv * g.x + be.x;
        r.y = (v[i].y - mean) * inv * g.y + be.y;
        r.z = (v[i].z - mean) * inv * g.z + be.z;
        r.w = (v[i].w - mean) * inv * g.w + be.w;
        o4[lane + i * 32] = r;
    }
}

// ---------------------------------------------------------------------------
// Router (unchanged).
// ---------------------------------------------------------------------------
__global__ __launch_bounds__(256) void router_kernel(
    const float* __restrict__ src, const float* __restrict__ rw,
    int* __restrict__ topi, float* __restrict__ topw)
{
    int w    = (blockIdx.x * 256 + threadIdx.x) >> 5;
    int lane = threadIdx.x & 31;
    const float* xr = src + (size_t)w * Dn;
    float acc[8] = {0, 0, 0, 0, 0, 0, 0, 0};
    for (int d = lane; d < Dn; d += 32) {
        float xv = xr[d];
        const float4* r4 = (const float4*)(rw + d * 8);
        float4 r0 = r4[0], r1 = r4[1];
        acc[0] += xv * r0.x; acc[1] += xv * r0.y; acc[2] += xv * r0.z; acc[3] += xv * r0.w;
        acc[4] += xv * r1.x; acc[5] += xv * r1.y; acc[6] += xv * r1.z; acc[7] += xv * r1.w;
    }
    #pragma unroll
    for (int e = 0; e < 8; e++)
        #pragma unroll
        for (int off = 16; off; off >>= 1)
            acc[e] += __shfl_xor_sync(0xffffffffu, acc[e], off);

    if (lane == 0) {
        float mx = acc[0];
        #pragma unroll
        for (int e = 1; e < 8; e++) mx = fmaxf(mx, acc[e]);
        float pe[8], sum = 0.0f;
        #pragma unroll
        for (int e = 0; e < 8; e++) { pe[e] = __expf(acc[e] - mx); sum += pe[e]; }
        float isum = 1.0f / sum;
        #pragma unroll
        for (int e = 0; e < 8; e++) pe[e] *= isum;
        int i1 = 0; float v1 = pe[0];
        #pragma unroll
        for (int e = 1; e < 8; e++) if (pe[e] > v1) { v1 = pe[e]; i1 = e; }
        int i2 = -1; float v2 = -1.0f;
        #pragma unroll
        for (int e = 0; e < 8; e++) if (e != i1 && pe[e] > v2) { v2 = pe[e]; i2 = e; }
        float wn = 1.0f / (v1 + v2);
        topi[2 * w]     = i1;  topi[2 * w + 1] = i2;
        topw[2 * w]     = v1 * wn;  topw[2 * w + 1] = v2 * wn;
    }
}

// ---------------------------------------------------------------------------
// Deterministic capacity scan (unchanged).
// ---------------------------------------------------------------------------
__global__ __launch_bounds__(1024) void scan_kernel(
    const int* __restrict__ topi, int* __restrict__ slotpos,
    int* __restrict__ ecnt)
{
    __shared__ int wtot[32][8];
    __shared__ int wbase[32][8];
    int tid = threadIdx.x, lane = tid & 31, wid = tid >> 5;
    int base = tid * 32;

    int eid[32];
    #pragma unroll
    for (int i = 0; i < 32; i++) eid[i] = topi[base + i];

    int c[8];
    #pragma unroll
    for (int e = 0; e < 8; e++) {
        int ce = 0;
        #pragma unroll
        for (int i = 0; i < 32; i++) ce += (eid[i] == e);
        c[e] = ce;
    }

    int inc[8], excl[8];
    #pragma unroll
    for (int e = 0; e < 8; e++) {
        int v = c[e];
        for (int off = 1; off < 32; off <<= 1) {
            int n = __shfl_up_sync(0xffffffffu, v, off);
            if (lane >= off) v += n;
        }
        inc[e] = v; excl[e] = v - c[e];
    }
    if (lane == 31) {
        #pragma unroll
        for (int e = 0; e < 8; e++) wtot[wid][e] = inc[e];
    }
    __syncthreads();
    if (wid == 0) {
        #pragma unroll
        for (int e = 0; e < 8; e++) {
            int t = wtot[lane][e];
            int v = t;
            for (int off = 1; off < 32; off <<= 1) {
                int n = __shfl_up_sync(0xffffffffu, v, off);
                if (lane >= off) v += n;
            }
            wbase[lane][e] = v - t;
            if (lane == 31) ecnt[e] = min(v, CAPn);
        }
    }
    __syncthreads();

    int run[8];
    #pragma unroll
    for (int e = 0; e < 8; e++) run[e] = wbase[wid][e] + excl[e];

    #pragma unroll
    for (int i = 0; i < 32; i++) {
        int e = eid[i];
        int p = 0;
        #pragma unroll
        for (int ee = 0; ee < 8; ee++)
            if (e == ee) { p = run[ee]; run[ee] = p + 1; }
        slotpos[base + i] = (p < CAPn) ? p : -1;
    }
}

// ---------------------------------------------------------------------------
// Scatter (unchanged).
// ---------------------------------------------------------------------------
__global__ __launch_bounds__(64) void scatter_kernel(
    const float* __restrict__ src, const int* __restrict__ topi,
    const int* __restrict__ slotpos, float* __restrict__ disp)
{
    int s = blockIdx.x;
    int p = slotpos[s];
    if (p < 0) return;
    int e   = topi[s];
    int tok = s >> 1;
    const float4* in4  = (const float4*)(src + (size_t)tok * Dn);
    float4*       out4 = (float4*)(disp + ((size_t)e * CAPn + p) * Dn);
    int t = threadIdx.x;
    out4[t]      = in4[t];
    out4[t + 64] = in4[t + 64];
}

// ---------------------------------------------------------------------------
// Combine + LN2 (unchanged).
// ---------------------------------------------------------------------------
__global__ __launch_bounds__(256) void combine_ln_kernel(
    const float* __restrict__ src, const float* __restrict__ y,
    const int* __restrict__ topi, const float* __restrict__ topw,
    const int* __restrict__ slotpos,
    const float* __restrict__ gam, const float* __restrict__ bet,
    float* __restrict__ out)
{
    int w    = (blockIdx.x * 256 + threadIdx.x) >> 5;
    int lane = threadIdx.x & 31;
    const float4* s4 = (const float4*)(src + (size_t)w * Dn);
    float4 v[4];
    #pragma unroll
    for (int i = 0; i < 4; i++) v[i] = s4[lane + i * 32];

    #pragma unroll
    for (int kk = 0; kk < 2; kk++) {
        int slot = 2 * w + kk;
        int p = slotpos[slot];
        if (p >= 0) {
            int e = topi[slot];
            float ww = topw[slot];
            const float4* y4 = (const float4*)(y + ((size_t)e * CAPn + p) * Dn);
            #pragma unroll
            for (int i = 0; i < 4; i++) {
                float4 yy = y4[lane + i * 32];
                v[i].x += ww * yy.x; v[i].y += ww * yy.y;
                v[i].z += ww * yy.z; v[i].w += ww * yy.w;
            }
        }
    }

    float s = 0.0f, s2 = 0.0f;
    #pragma unroll
    for (int i = 0; i < 4; i++) {
        s  += v[i].x + v[i].y + v[i].z + v[i].w;
        s2 += v[i].x * v[i].x + v[i].y * v[i].y + v[i].z * v[i].z + v[i].w * v[i].w;
    }
    #pragma unroll
    for (int off = 16; off; off >>= 1) {
        s  += __shfl_xor_sync(0xffffffffu, s,  off);
        s2 += __shfl_xor_sync(0xffffffffu, s2, off);
    }
    float mean = s * (1.0f / Dn);
    float var  = s2 * (1.0f / Dn) - mean * mean;
    float inv  = rsqrtf(var + 1e-5f);
    const float4* g4 = (const float4*)gam;
    const float4* b4 = (const float4*)bet;
    float4* o4 = (float4*)(out + (size_t)w * Dn);
    #pragma unroll
    for (int i = 0; i < 4; i++) {
        float4 g = g4[lane + i * 32], be = b4[lane + i * 32];
        float4 r;
        r.x = (v[i].x - mean) * inv * g.x + be.x;
        r.y = (v[i].y - mean) * inv * g.y + be.y;
        r.z = (v[i].z - mean) * inv * g.z + be.z;
        r.w = (v[i].w - mean) * inv * g.w + be.w;
        o4[lane + i * 32] = r;
    }
}

// ---------------------------------------------------------------------------
// Launch sequence
// ---------------------------------------------------------------------------
extern "C" void kernel_launch(void* const* d_in, const int* in_sizes, int n_in,
                              void* d_out, int out_size)
{
    const float* x    = (const float*)d_in[0];
    const int*   msk  = (const int*)  d_in[1];
    const float* wq   = (const float*)d_in[2];
    const float* bq   = (const float*)d_in[3];
    const float* wk   = (const float*)d_in[4];
    const float* bk   = (const float*)d_in[5];
    const float* wv   = (const float*)d_in[6];
    const float* bv   = (const float*)d_in[7];
    const float* wo   = (const float*)d_in[8];
    const float* bo   = (const float*)d_in[9];
    const float* ln1g = (const float*)d_in[10];
    const float* ln1b = (const float*)d_in[11];
    const float* ln2g = (const float*)d_in[12];
    const float* ln2b = (const float*)d_in[13];
    const float* rw   = (const float*)d_in[14];
    const float* w1   = (const float*)d_in[15];
    const float* b1   = (const float*)d_in[16];
    const float* w2   = (const float*)d_in[17];
    const float* b2   = (const float*)d_in[18];
    float* out = (float*)d_out;

    float* S = nullptr;
    int*   I = nullptr;
    cudaGetSymbolAddress((void**)&S, g_scratch);
    cudaGetSymbolAddress((void**)&I, g_iscratch);

    float* Qb   = S + OFF_Q;
    float* Kbuf = S + OFF_K;
    float* Vb   = S + OFF_V;
    float* ATT  = S + OFF_ATTN;
    float* PRJ  = S + OFF_PRJ;
    float* SRC  = S + OFF_SRC;
    float* DISP = S + OFF_DISP;
    float* Hb   = S + OFF_H;
    float* Yb   = S + OFF_Y;
    float* TW   = S + OFF_TOPW;
    int* topi    = I;
    int* slotpos = I + NSLOT;
    int* ecnt    = I + 2 * NSLOT;

    dim3 blk(256);
    dim3 gproj(Dn / BN, Tn / BM);     // (4, 128)

    // --- attention block ---
    gemm_tf32_kernel<false><<<gproj, blk>>>(x, Dn, wq, Dn, bq, Qb,   Dn, Dn, nullptr);
    gemm_tf32_kernel<false><<<gproj, blk>>>(x, Dn, wk, Dn, bk, Kbuf, Dn, Dn, nullptr);
    gemm_tf32_kernel<false><<<gproj, blk>>>(x, Dn, wv, Dn, bv, Vb,   Dn, Dn, nullptr);
    attn_mma_kernel<<<dim3(Cn / 64, Bn * Hn), 128>>>(Qb, Kbuf, Vb, msk, ATT);
    gemm_tf32_kernel<false><<<gproj, blk>>>(ATT, Dn, wo, Dn, bo, PRJ, Dn, Dn, nullptr);
    add_ln_kernel<<<Tn / 8, 256>>>(x, PRJ, ln1g, ln1b, SRC);

    // --- MoE block ---
    router_kernel<<<Tn / 8, 256>>>(SRC, rw, topi, TW);
    scan_kernel<<<1, 1024>>>(topi, slotpos, ecnt);
    scatter_kernel<<<NSLOT, 64>>>(SRC, topi, slotpos, DISP);

    for (int e = 0; e < En; e++) {
        gemm_tf32_kernel<true><<<dim3(FFn / BN, CAPn / BM), blk>>>(
            DISP + (size_t)e * CAPn * Dn, Dn,
            w1 + (size_t)e * Dn * FFn, FFn,
            b1 + (size_t)e * FFn,
            Hb, FFn,
            Dn, ecnt + e);
        gemm_tf32_kernel<false><<<dim3(Dn / BN, CAPn / BM), blk>>>(
            Hb, FFn,
            w2 + (size_t)e * FFn * Dn, Dn,
            b2 + (size_t)e * Dn,
            Yb + (size_t)e * CAPn * Dn, Dn,
            FFn, ecnt + e);
    }

    combine_ln_kernel<<<Tn / 8, 256>>>(SRC, Yb, topi, TW, slotpos,
                                       ln2g, ln2b, out);
}

// round 6
// speedup vs baseline: 3.2383x; 1.3531x over previous
#include <cuda_runtime.h>
#include <math.h>
#include <stdint.h>

// ---------------------------------------------------------------------------
// Problem constants
// ---------------------------------------------------------------------------
#define Bn    16
#define Cn    1024
#define Dn    512
#define Hn    8
#define HDn   64
#define En    8
#define Ktop  2
#define FFn   2048
#define Tn    (Bn*Cn)        /* 16384 tokens */
#define CAPn  5120
#define NSLOT (Tn*Ktop)      /* 32768 slots  */

// ---------------------------------------------------------------------------
// Scratch (~571 MB): Q|K|V|ATT for attention; PRJ aliases Q, SRC aliases K,
// DISP overlays V/ATT; full per-expert H and Y for batched expert GEMMs.
// ---------------------------------------------------------------------------
static constexpr size_t NPROJ    = (size_t)Tn * Dn;
static constexpr size_t OFF_Q    = 0;
static constexpr size_t OFF_K    = 1 * NPROJ;
static constexpr size_t OFF_V    = 2 * NPROJ;
static constexpr size_t OFF_ATTN = 3 * NPROJ;
static constexpr size_t OFF_PRJ  = OFF_Q;
static constexpr size_t OFF_SRC  = OFF_K;
static constexpr size_t OFF_DISP = OFF_V;
static constexpr size_t NDISP    = (size_t)En * CAPn * Dn;
static constexpr size_t OFF_H    = OFF_DISP + NDISP;
static constexpr size_t NH       = (size_t)En * CAPn * FFn;
static constexpr size_t OFF_Y    = OFF_H + NH;
static constexpr size_t OFF_TOPW = OFF_Y + NDISP;
static constexpr size_t SCRATCH_FLOATS = OFF_TOPW + NSLOT;

__device__ float g_scratch[SCRATCH_FLOATS];
__device__ int   g_iscratch[2 * NSLOT + 8];

// ---------------------------------------------------------------------------
static __device__ __forceinline__ float gelu_fn(float x) {
    float x3 = x * x * x;
    float u  = 0.7978845608028654f * (x + 0.044715f * x3);
    return 0.5f * x * (1.0f + tanhf(u));
}

static __device__ __forceinline__ uint32_t f2tf(float x) {
    uint32_t u;
    asm("cvt.rna.tf32.f32 %0, %1;" : "=r"(u) : "f"(x));
    return u;
}

#define MMA_TF32(acc, a, b0, b1)                                              \
    asm volatile(                                                             \
        "mma.sync.aligned.m16n8k8.row.col.f32.tf32.tf32.f32 "                 \
        "{%0,%1,%2,%3}, {%4,%5,%6,%7}, {%8,%9}, {%0,%1,%2,%3};"               \
        : "+f"(acc[0]), "+f"(acc[1]), "+f"(acc[2]), "+f"(acc[3])              \
        : "r"(a[0]), "r"(a[1]), "r"(a[2]), "r"(a[3]), "r"(b0), "r"(b1))

static __device__ __forceinline__ void cp_async16(uint32_t saddr, const float* g) {
    asm volatile("cp.async.cg.shared.global [%0], [%1], 16;" :: "r"(saddr), "l"(g));
}

// ---------------------------------------------------------------------------
// tf32 tensor-core GEMM, 2-stage cp.async pipeline, z-batched.
//   C[z][M,N] = A[z][M,K] @ B[z][K,N] + bias[z]   (opt GELU)
// 128x128x32 tile, 256 threads (8 warps, 2x4), warp tile 64x32.
// Smem (dynamic, 70KB): A stages [2][128][36] fp32, B stages [2][32][136].
// tf32 cvt at fragment-load time (keeps rna rounding). mcount[z] early-exit.
// ---------------------------------------------------------------------------
#define BM 128
#define BN 128
#define BKt 32
#define ASTRIDE 36
#define BSTRIDE 136
#define ASTAGE (BM * ASTRIDE)              // 4608 floats
#define BSTAGE (BKt * BSTRIDE)             // 4352 floats
#define GEMM_SMEM_BYTES ((2 * (ASTAGE + BSTAGE)) * 4)   // 71680

template <bool GELU>
__global__ __launch_bounds__(256) void gemm_tf32_kernel(
    const float* __restrict__ A, int lda, size_t aZ,
    const float* __restrict__ Bm, int ldb, size_t bZ,
    const float* __restrict__ bias, int biasZ,
    float* __restrict__ C, int ldc, size_t cZ,
    int Kd, const int* __restrict__ mcount)
{
    const int z = blockIdx.z;
    if (mcount && (int)(blockIdx.y * BM) >= mcount[z]) return;

    extern __shared__ float dsm[];
    float* Asm = dsm;                       // [2][BM][ASTRIDE]
    float* Bsm = dsm + 2 * ASTAGE;          // [2][BKt][BSTRIDE]

    const int tid  = threadIdx.x;
    const int wid  = tid >> 5;
    const int lane = tid & 31;
    const int wm   = (wid & 1) * 64;
    const int wnn  = (wid >> 1) * 32;
    const int g    = lane >> 2;
    const int tg   = lane & 3;

    // staging assignments (16 floats = 4 x float4 per thread per tile)
    const int ar  = tid >> 1;
    const int ac0 = (tid & 1) * 16;
    const int br  = tid >> 3;
    const int bc0 = (tid & 7) * 16;

    const float* Ag = A + z * aZ + (size_t)(blockIdx.y * BM + ar) * lda + ac0;
    const float* Bg = Bm + z * bZ + (size_t)br * ldb + blockIdx.x * BN + bc0;

    const uint32_t asb = (uint32_t)__cvta_generic_to_shared(Asm) +
                         (ar * ASTRIDE + ac0) * 4;
    const uint32_t bsb = (uint32_t)__cvta_generic_to_shared(Bsm) +
                         (br * BSTRIDE + bc0) * 4;

    const int ntile = Kd / BKt;

    // prefetch stage 0
    {
        const float* ga = Ag;
        const float* gb = Bg;
        #pragma unroll
        for (int j = 0; j < 4; j++) cp_async16(asb + j * 16, ga + j * 4);
        #pragma unroll
        for (int j = 0; j < 4; j++) cp_async16(bsb + j * 16, gb + j * 4);
        asm volatile("cp.async.commit_group;");
    }

    float acc[4][4][4];
    #pragma unroll
    for (int i = 0; i < 4; i++)
        #pragma unroll
        for (int j = 0; j < 4; j++) {
            acc[i][j][0] = 0.f; acc[i][j][1] = 0.f;
            acc[i][j][2] = 0.f; acc[i][j][3] = 0.f;
        }

    for (int kt = 0; kt < ntile; kt++) {
        const int buf = kt & 1;
        if (kt + 1 < ntile) {
            const int nbuf = buf ^ 1;
            const float* ga = Ag + (kt + 1) * BKt;
            const float* gb = Bg + (size_t)(kt + 1) * BKt * ldb;
            uint32_t sa = asb + nbuf * (ASTAGE * 4);
            uint32_t sb = bsb + nbuf * (BSTAGE * 4);
            #pragma unroll
            for (int j = 0; j < 4; j++) cp_async16(sa + j * 16, ga + j * 4);
            #pragma unroll
            for (int j = 0; j < 4; j++) cp_async16(sb + j * 16, gb + j * 4);
            asm volatile("cp.async.commit_group;");
            asm volatile("cp.async.wait_group 1;");
        } else {
            asm volatile("cp.async.wait_group 0;");
        }
        __syncthreads();

        const float* Ab = Asm + buf * ASTAGE;
        const float* Bb = Bsm + buf * BSTAGE;

        #pragma unroll
        for (int kc = 0; kc < 4; kc++) {
            const int k0 = kc * 8;
            uint32_t afr[4][4];
            #pragma unroll
            for (int i = 0; i < 4; i++) {
                const float* ra = Ab + (wm + i * 16 + g) * ASTRIDE + k0;
                const float* rb = Ab + (wm + i * 16 + g + 8) * ASTRIDE + k0;
                afr[i][0] = f2tf(ra[tg]);
                afr[i][1] = f2tf(rb[tg]);
                afr[i][2] = f2tf(ra[tg + 4]);
                afr[i][3] = f2tf(rb[tg + 4]);
            }
            uint32_t bfr[4][2];
            #pragma unroll
            for (int j = 0; j < 4; j++) {
                int n = wnn + j * 8 + g;
                bfr[j][0] = f2tf(Bb[(k0 + tg) * BSTRIDE + n]);
                bfr[j][1] = f2tf(Bb[(k0 + tg + 4) * BSTRIDE + n]);
            }
            #pragma unroll
            for (int i = 0; i < 4; i++)
                #pragma unroll
                for (int j = 0; j < 4; j++)
                    MMA_TF32(acc[i][j], afr[i], bfr[j][0], bfr[j][1]);
        }
        __syncthreads();
    }

    // epilogue
    const float* bz = bias + (size_t)z * biasZ;
    float* Cz = C + z * cZ;
    #pragma unroll
    for (int j = 0; j < 4; j++) {
        const int col = blockIdx.x * BN + wnn + j * 8 + 2 * tg;
        const float2 bb = *(const float2*)(bz + col);
        #pragma unroll
        for (int i = 0; i < 4; i++) {
            const size_t row0 = (size_t)blockIdx.y * BM + wm + i * 16 + g;
            float2 v0, v1;
            v0.x = acc[i][j][0] + bb.x;
            v0.y = acc[i][j][1] + bb.y;
            v1.x = acc[i][j][2] + bb.x;
            v1.y = acc[i][j][3] + bb.y;
            if (GELU) {
                v0.x = gelu_fn(v0.x); v0.y = gelu_fn(v0.y);
                v1.x = gelu_fn(v1.x); v1.y = gelu_fn(v1.y);
            }
            *(float2*)(Cz + row0 * ldc + col)       = v0;
            *(float2*)(Cz + (row0 + 8) * ldc + col) = v1;
        }
    }
}

// ---------------------------------------------------------------------------
// Flash attention, tf32 tensor cores (verified R5, unchanged).
// ---------------------------------------------------------------------------
__global__ __launch_bounds__(128) void attn_mma_kernel(
    const float* __restrict__ Q, const float* __restrict__ Kb,
    const float* __restrict__ V, const int* __restrict__ mask,
    float* __restrict__ O)
{
    __shared__ uint32_t sK[64][68];
    __shared__ uint32_t sV[64][72];
    __shared__ uint32_t sP[4][16][36];
    __shared__ int      sM[64];

    const int tid  = threadIdx.x;
    const int w    = tid >> 5;
    const int lane = tid & 31;
    const int g    = lane >> 2;
    const int tg   = lane & 3;

    const int bh = blockIdx.y;
    const int b  = bh >> 3, h = bh & 7;
    const int q0 = blockIdx.x << 6;
    const size_t rowbase = (size_t)b * Cn;

    const float* QB = Q  + (rowbase + q0) * Dn + h * HDn;
    const float* KB = Kb + rowbase * Dn + h * HDn;
    const float* VB = V  + rowbase * Dn + h * HDn;
    const int*   MB = mask + b * Cn;

    #pragma unroll
    for (int i = 0; i < 8; i++) {
        int slot = tid + i * 128;
        int r = slot >> 4, c4 = (slot & 15) << 2;
        float4 qv = *(const float4*)(QB + (size_t)r * Dn + c4);
        sK[r][c4 + 0] = f2tf(qv.x * 0.125f);
        sK[r][c4 + 1] = f2tf(qv.y * 0.125f);
        sK[r][c4 + 2] = f2tf(qv.z * 0.125f);
        sK[r][c4 + 3] = f2tf(qv.w * 0.125f);
    }
    __syncthreads();

    const int row0 = w * 16 + g;
    uint32_t qa[8][4];
    #pragma unroll
    for (int ks = 0; ks < 8; ks++) {
        qa[ks][0] = sK[row0][8 * ks + tg];
        qa[ks][1] = sK[row0 + 8][8 * ks + tg];
        qa[ks][2] = sK[row0][8 * ks + tg + 4];
        qa[ks][3] = sK[row0 + 8][8 * ks + tg + 4];
    }
    __syncthreads();

    float o[8][4];
    #pragma unroll
    for (int jn = 0; jn < 8; jn++) {
        o[jn][0] = 0.f; o[jn][1] = 0.f; o[jn][2] = 0.f; o[jn][3] = 0.f;
    }
    float mrun0 = -3.0e38f, mrun1 = -3.0e38f;
    float lrun0 = 0.f, lrun1 = 0.f;

    for (int kt = 0; kt < Cn / 64; kt++) {
        const int k0 = kt * 64;
        #pragma unroll
        for (int i = 0; i < 8; i++) {
            int slot = tid + i * 128;
            int r = slot >> 4, c4 = (slot & 15) << 2;
            float4 kv = *(const float4*)(KB + (size_t)(k0 + r) * Dn + c4);
            float4 vv = *(const float4*)(VB + (size_t)(k0 + r) * Dn + c4);
            sK[r][c4 + 0] = f2tf(kv.x); sK[r][c4 + 1] = f2tf(kv.y);
            sK[r][c4 + 2] = f2tf(kv.z); sK[r][c4 + 3] = f2tf(kv.w);
            sV[r][c4 + 0] = f2tf(vv.x); sV[r][c4 + 1] = f2tf(vv.y);
            sV[r][c4 + 2] = f2tf(vv.z); sV[r][c4 + 3] = f2tf(vv.w);
        }
        if (tid < 64) sM[tid] = MB[k0 + tid];
        __syncthreads();

        #pragma unroll
        for (int kc = 0; kc < 2; kc++) {
            float sacc[4][4];
            #pragma unroll
            for (int j = 0; j < 4; j++) {
                sacc[j][0] = 0.f; sacc[j][1] = 0.f;
                sacc[j][2] = 0.f; sacc[j][3] = 0.f;
            }
            #pragma unroll
            for (int ks = 0; ks < 8; ks++) {
                #pragma unroll
                for (int j = 0; j < 4; j++) {
                    int n = kc * 32 + 8 * j + g;
                    uint32_t b0 = sK[n][8 * ks + tg];
                    uint32_t b1 = sK[n][8 * ks + tg + 4];
                    MMA_TF32(sacc[j], qa[ks], b0, b1);
                }
            }

            #pragma unroll
            for (int j = 0; j < 4; j++) {
                int c = kc * 32 + 8 * j + 2 * tg;
                if (sM[c] == 0)     { sacc[j][0] = -1e10f; sacc[j][2] = -1e10f; }
                if (sM[c + 1] == 0) { sacc[j][1] = -1e10f; sacc[j][3] = -1e10f; }
            }

            float mx0 = -3.0e38f, mx1 = -3.0e38f;
            #pragma unroll
            for (int j = 0; j < 4; j++) {
                mx0 = fmaxf(mx0, fmaxf(sacc[j][0], sacc[j][1]));
                mx1 = fmaxf(mx1, fmaxf(sacc[j][2], sacc[j][3]));
            }
            mx0 = fmaxf(mx0, __shfl_xor_sync(0xffffffffu, mx0, 1));
            mx0 = fmaxf(mx0, __shfl_xor_sync(0xffffffffu, mx0, 2));
            mx1 = fmaxf(mx1, __shfl_xor_sync(0xffffffffu, mx1, 1));
            mx1 = fmaxf(mx1, __shfl_xor_sync(0xffffffffu, mx1, 2));

            float mnew0 = fmaxf(mrun0, mx0);
            float mnew1 = fmaxf(mrun1, mx1);
            float corr0 = __expf(mrun0 - mnew0);
            float corr1 = __expf(mrun1 - mnew1);
            mrun0 = mnew0; mrun1 = mnew1;

            float p[4][4];
            float ls0 = 0.f, ls1 = 0.f;
            #pragma unroll
            for (int j = 0; j < 4; j++) {
                p[j][0] = __expf(sacc[j][0] - mnew0);
                p[j][1] = __expf(sacc[j][1] - mnew0);
                p[j][2] = __expf(sacc[j][2] - mnew1);
                p[j][3] = __expf(sacc[j][3] - mnew1);
                ls0 += p[j][0] + p[j][1];
                ls1 += p[j][2] + p[j][3];
            }
            ls0 += __shfl_xor_sync(0xffffffffu, ls0, 1);
            ls0 += __shfl_xor_sync(0xffffffffu, ls0, 2);
            ls1 += __shfl_xor_sync(0xffffffffu, ls1, 1);
            ls1 += __shfl_xor_sync(0xffffffffu, ls1, 2);
            lrun0 = lrun0 * corr0 + ls0;
            lrun1 = lrun1 * corr1 + ls1;

            #pragma unroll
            for (int jn = 0; jn < 8; jn++) {
                o[jn][0] *= corr0; o[jn][1] *= corr0;
                o[jn][2] *= corr1; o[jn][3] *= corr1;
            }

            #pragma unroll
            for (int j = 0; j < 4; j++) {
                int c = 8 * j + 2 * tg;
                sP[w][g][c]         = f2tf(p[j][0]);
                sP[w][g][c + 1]     = f2tf(p[j][1]);
                sP[w][g + 8][c]     = f2tf(p[j][2]);
                sP[w][g + 8][c + 1] = f2tf(p[j][3]);
            }
            __syncwarp();

            uint32_t pa[4][4];
            #pragma unroll
            for (int ks = 0; ks < 4; ks++) {
                pa[ks][0] = sP[w][g][8 * ks + tg];
                pa[ks][1] = sP[w][g + 8][8 * ks + tg];
                pa[ks][2] = sP[w][g][8 * ks + tg + 4];
                pa[ks][3] = sP[w][g + 8][8 * ks + tg + 4];
            }
            __syncwarp();

            #pragma unroll
            for (int ks = 0; ks < 4; ks++) {
                int kr = kc * 32 + 8 * ks;
                #pragma unroll
                for (int jn = 0; jn < 8; jn++) {
                    uint32_t b0 = sV[kr + tg][8 * jn + g];
                    uint32_t b1 = sV[kr + tg + 4][8 * jn + g];
                    MMA_TF32(o[jn], pa[ks], b0, b1);
                }
            }
        }
        __syncthreads();
    }

    const float inv0 = 1.0f / lrun0;
    const float inv1 = 1.0f / lrun1;
    const size_t grow = rowbase + q0 + row0;
    #pragma unroll
    for (int jn = 0; jn < 8; jn++) {
        int col = h * HDn + 8 * jn + 2 * tg;
        float2 v0, v1;
        v0.x = o[jn][0] * inv0; v0.y = o[jn][1] * inv0;
        v1.x = o[jn][2] * inv1; v1.y = o[jn][3] * inv1;
        *(float2*)(O + grow * Dn + col)       = v0;
        *(float2*)(O + (grow + 8) * Dn + col) = v1;
    }
}

// ---------------------------------------------------------------------------
// Residual add + LayerNorm (unchanged).
// ---------------------------------------------------------------------------
__global__ __launch_bounds__(256) void add_ln_kernel(
    const float* __restrict__ A, const float* __restrict__ R,
    const float* __restrict__ gam, const float* __restrict__ bet,
    float* __restrict__ out)
{
    int w    = (blockIdx.x * 256 + threadIdx.x) >> 5;
    int lane = threadIdx.x & 31;
    const float4* a4 = (const float4*)(A + (size_t)w * Dn);
    const float4* r4 = (const float4*)(R + (size_t)w * Dn);
    float4 v[4];
    float s = 0.0f, s2 = 0.0f;
    #pragma unroll
    for (int i = 0; i < 4; i++) {
        float4 xa = a4[lane + i * 32], xr = r4[lane + i * 32];
        v[i].x = xa.x + xr.x; v[i].y = xa.y + xr.y;
        v[i].z = xa.z + xr.z; v[i].w = xa.w + xr.w;
        s  += v[i].x + v[i].y + v[i].z + v[i].w;
        s2 += v[i].x * v[i].x + v[i].y * v[i].y + v[i].z * v[i].z + v[i].w * v[i].w;
    }
    #pragma unroll
    for (int off = 16; off; off >>= 1) {
        s  += __shfl_xor_sync(0xffffffffu, s,  off);
        s2 += __shfl_xor_sync(0xffffffffu, s2, off);
    }
    float mean = s * (1.0f / Dn);
    float var  = s2 * (1.0f / Dn) - mean * mean;
    float inv  = rsqrtf(var + 1e-5f);
    const float4* g4 = (const float4*)gam;
    const float4* b4 = (const float4*)bet;
    float4* o4 = (float4*)(out + (size_t)w * Dn);
    #pragma unroll
    for (int i = 0; i < 4; i++) {
        float4 g = g4[lane + i * 32], be = b4[lane + i * 32];
        float4 r;
        r.x = (v[i].x - mean) * inv * g.x + be.x;
        r.y = (v[i].y - mean) * inv * g.y + be.y;
        r.z = (v[i].z - mean) * inv * g.z + be.z;
        r.w = (v[i].w - mean) * inv * g.w + be.w;
        o4[lane + i * 32] = r;
    }
}

// ---------------------------------------------------------------------------
// Router (unchanged).
// ---------------------------------------------------------------------------
__global__ __launch_bounds__(256) void router_kernel(
    const float* __restrict__ src, const float* __restrict__ rw,
    int* __restrict__ topi, float* __restrict__ topw)
{
    int w    = (blockIdx.x * 256 + threadIdx.x) >> 5;
    int lane = threadIdx.x & 31;
    const float* xr = src + (size_t)w * Dn;
    float acc[8] = {0, 0, 0, 0, 0, 0, 0, 0};
    for (int d = lane; d < Dn; d += 32) {
        float xv = xr[d];
        const float4* r4 = (const float4*)(rw + d * 8);
        float4 r0 = r4[0], r1 = r4[1];
        acc[0] += xv * r0.x; acc[1] += xv * r0.y; acc[2] += xv * r0.z; acc[3] += xv * r0.w;
        acc[4] += xv * r1.x; acc[5] += xv * r1.y; acc[6] += xv * r1.z; acc[7] += xv * r1.w;
    }
    #pragma unroll
    for (int e = 0; e < 8; e++)
        #pragma unroll
        for (int off = 16; off; off >>= 1)
            acc[e] += __shfl_xor_sync(0xffffffffu, acc[e], off);

    if (lane == 0) {
        float mx = acc[0];
        #pragma unroll
        for (int e = 1; e < 8; e++) mx = fmaxf(mx, acc[e]);
        float pe[8], sum = 0.0f;
        #pragma unroll
        for (int e = 0; e < 8; e++) { pe[e] = __expf(acc[e] - mx); sum += pe[e]; }
        float isum = 1.0f / sum;
        #pragma unroll
        for (int e = 0; e < 8; e++) pe[e] *= isum;
        int i1 = 0; float v1 = pe[0];
        #pragma unroll
        for (int e = 1; e < 8; e++) if (pe[e] > v1) { v1 = pe[e]; i1 = e; }
        int i2 = -1; float v2 = -1.0f;
        #pragma unroll
        for (int e = 0; e < 8; e++) if (e != i1 && pe[e] > v2) { v2 = pe[e]; i2 = e; }
        float wn = 1.0f / (v1 + v2);
        topi[2 * w]     = i1;  topi[2 * w + 1] = i2;
        topw[2 * w]     = v1 * wn;  topw[2 * w + 1] = v2 * wn;
    }
}

// ---------------------------------------------------------------------------
// Deterministic capacity scan (unchanged).
// ---------------------------------------------------------------------------
__global__ __launch_bounds__(1024) void scan_kernel(
    const int* __restrict__ topi, int* __restrict__ slotpos,
    int* __restrict__ ecnt)
{
    __shared__ int wtot[32][8];
    __shared__ int wbase[32][8];
    int tid = threadIdx.x, lane = tid & 31, wid = tid >> 5;
    int base = tid * 32;

    int eid[32];
    #pragma unroll
    for (int i = 0; i < 32; i++) eid[i] = topi[base + i];

    int c[8];
    #pragma unroll
    for (int e = 0; e < 8; e++) {
        int ce = 0;
        #pragma unroll
        for (int i = 0; i < 32; i++) ce += (eid[i] == e);
        c[e] = ce;
    }

    int inc[8], excl[8];
    #pragma unroll
    for (int e = 0; e < 8; e++) {
        int v = c[e];
        for (int off = 1; off < 32; off <<= 1) {
            int n = __shfl_up_sync(0xffffffffu, v, off);
            if (lane >= off) v += n;
        }
        inc[e] = v; excl[e] = v - c[e];
    }
    if (lane == 31) {
        #pragma unroll
        for (int e = 0; e < 8; e++) wtot[wid][e] = inc[e];
    }
    __syncthreads();
    if (wid == 0) {
        #pragma unroll
        for (int e = 0; e < 8; e++) {
            int t = wtot[lane][e];
            int v = t;
            for (int off = 1; off < 32; off <<= 1) {
                int n = __shfl_up_sync(0xffffffffu, v, off);
                if (lane >= off) v += n;
            }
            wbase[lane][e] = v - t;
            if (lane == 31) ecnt[e] = min(v, CAPn);
        }
    }
    __syncthreads();

    int run[8];
    #pragma unroll
    for (int e = 0; e < 8; e++) run[e] = wbase[wid][e] + excl[e];

    #pragma unroll
    for (int i = 0; i < 32; i++) {
        int e = eid[i];
        int p = 0;
        #pragma unroll
        for (int ee = 0; ee < 8; ee++)
            if (e == ee) { p = run[ee]; run[ee] = p + 1; }
        slotpos[base + i] = (p < CAPn) ? p : -1;
    }
}

// ---------------------------------------------------------------------------
// Scatter (unchanged).
// ---------------------------------------------------------------------------
__global__ __launch_bounds__(64) void scatter_kernel(
    const float* __restrict__ src, const int* __restrict__ topi,
    const int* __restrict__ slotpos, float* __restrict__ disp)
{
    int s = blockIdx.x;
    int p = slotpos[s];
    if (p < 0) return;
    int e   = topi[s];
    int tok = s >> 1;
    const float4* in4  = (const float4*)(src + (size_t)tok * Dn);
    float4*       out4 = (float4*)(disp + ((size_t)e * CAPn + p) * Dn);
    int t = threadIdx.x;
    out4[t]      = in4[t];
    out4[t + 64] = in4[t + 64];
}

// ---------------------------------------------------------------------------
// Combine + LN2 (unchanged).
// ---------------------------------------------------------------------------
__global__ __launch_bounds__(256) void combine_ln_kernel(
    const float* __restrict__ src, const float* __restrict__ y,
    const int* __restrict__ topi, const float* __restrict__ topw,
    const int* __restrict__ slotpos,
    const float* __restrict__ gam, const float* __restrict__ bet,
    float* __restrict__ out)
{
    int w    = (blockIdx.x * 256 + threadIdx.x) >> 5;
    int lane = threadIdx.x & 31;
    const float4* s4 = (const float4*)(src + (size_t)w * Dn);
    float4 v[4];
    #pragma unroll
    for (int i = 0; i < 4; i++) v[i] = s4[lane + i * 32];

    #pragma unroll
    for (int kk = 0; kk < 2; kk++) {
        int slot = 2 * w + kk;
        int p = slotpos[slot];
        if (p >= 0) {
            int e = topi[slot];
            float ww = topw[slot];
            const float4* y4 = (const float4*)(y + ((size_t)e * CAPn + p) * Dn);
            #pragma unroll
            for (int i = 0; i < 4; i++) {
                float4 yy = y4[lane + i * 32];
                v[i].x += ww * yy.x; v[i].y += ww * yy.y;
                v[i].z += ww * yy.z; v[i].w += ww * yy.w;
            }
        }
    }

    float s = 0.0f, s2 = 0.0f;
    #pragma unroll
    for (int i = 0; i < 4; i++) {
        s  += v[i].x + v[i].y + v[i].z + v[i].w;
        s2 += v[i].x * v[i].x + v[i].y * v[i].y + v[i].z * v[i].z + v[i].w * v[i].w;
    }
    #pragma unroll
    for (int off = 16; off; off >>= 1) {
        s  += __shfl_xor_sync(0xffffffffu, s,  off);
        s2 += __shfl_xor_sync(0xffffffffu, s2, off);
    }
    float mean = s * (1.0f / Dn);
    float var  = s2 * (1.0f / Dn) - mean * mean;
    float inv  = rsqrtf(var + 1e-5f);
    const float4* g4 = (const float4*)gam;
    const float4* b4 = (const float4*)bet;
    float4* o4 = (float4*)(out + (size_t)w * Dn);
    #pragma unroll
    for (int i = 0; i < 4; i++) {
        float4 g = g4[lane + i * 32], be = b4[lane + i * 32];
        float4 r;
        r.x = (v[i].x - mean) * inv * g.x + be.x;
        r.y = (v[i].y - mean) * inv * g.y + be.y;
        r.z = (v[i].z - mean) * inv * g.z + be.z;
        r.w = (v[i].w - mean) * inv * g.w + be.w;
        o4[lane + i * 32] = r;
    }
}

// ---------------------------------------------------------------------------
// Launch sequence
// ---------------------------------------------------------------------------
extern "C" void kernel_launch(void* const* d_in, const int* in_sizes, int n_in,
                              void* d_out, int out_size)
{
    const float* x    = (const float*)d_in[0];
    const int*   msk  = (const int*)  d_in[1];
    const float* wq   = (const float*)d_in[2];
    const float* bq   = (const float*)d_in[3];
    const float* wk   = (const float*)d_in[4];
    const float* bk   = (const float*)d_in[5];
    const float* wv   = (const float*)d_in[6];
    const float* bv   = (const float*)d_in[7];
    const float* wo   = (const float*)d_in[8];
    const float* bo   = (const float*)d_in[9];
    const float* ln1g = (const float*)d_in[10];
    const float* ln1b = (const float*)d_in[11];
    const float* ln2g = (const float*)d_in[12];
    const float* ln2b = (const float*)d_in[13];
    const float* rw   = (const float*)d_in[14];
    const float* w1   = (const float*)d_in[15];
    const float* b1   = (const float*)d_in[16];
    const float* w2   = (const float*)d_in[17];
    const float* b2   = (const float*)d_in[18];
    float* out = (float*)d_out;

    float* S = nullptr;
    int*   I = nullptr;
    cudaGetSymbolAddress((void**)&S, g_scratch);
    cudaGetSymbolAddress((void**)&I, g_iscratch);

    float* Qb   = S + OFF_Q;
    float* Kbuf = S + OFF_K;
    float* Vb   = S + OFF_V;
    float* ATT  = S + OFF_ATTN;
    float* PRJ  = S + OFF_PRJ;
    float* SRC  = S + OFF_SRC;
    float* DISP = S + OFF_DISP;
    float* Hb   = S + OFF_H;
    float* Yb   = S + OFF_Y;
    float* TW   = S + OFF_TOPW;
    int* topi    = I;
    int* slotpos = I + NSLOT;
    int* ecnt    = I + 2 * NSLOT;

    cudaFuncSetAttribute(gemm_tf32_kernel<false>,
                         cudaFuncAttributeMaxDynamicSharedMemorySize,
                         GEMM_SMEM_BYTES);
    cudaFuncSetAttribute(gemm_tf32_kernel<true>,
                         cudaFuncAttributeMaxDynamicSharedMemorySize,
                         GEMM_SMEM_BYTES);

    dim3 blk(256);
    dim3 gproj(Dn / BN, Tn / BM, 1);

    // --- attention block ---
    gemm_tf32_kernel<false><<<gproj, blk, GEMM_SMEM_BYTES>>>(
        x, Dn, 0, wq, Dn, 0, bq, 0, Qb, Dn, 0, Dn, nullptr);
    gemm_tf32_kernel<false><<<gproj, blk, GEMM_SMEM_BYTES>>>(
        x, Dn, 0, wk, Dn, 0, bk, 0, Kbuf, Dn, 0, Dn, nullptr);
    gemm_tf32_kernel<false><<<gproj, blk, GEMM_SMEM_BYTES>>>(
        x, Dn, 0, wv, Dn, 0, bv, 0, Vb, Dn, 0, Dn, nullptr);
    attn_mma_kernel<<<dim3(Cn / 64, Bn * Hn), 128>>>(Qb, Kbuf, Vb, msk, ATT);
    gemm_tf32_kernel<false><<<gproj, blk, GEMM_SMEM_BYTES>>>(
        ATT, Dn, 0, wo, Dn, 0, bo, 0, PRJ, Dn, 0, Dn, nullptr);
    add_ln_kernel<<<Tn / 8, 256>>>(x, PRJ, ln1g, ln1b, SRC);

    // --- MoE block ---
    router_kernel<<<Tn / 8, 256>>>(SRC, rw, topi, TW);
    scan_kernel<<<1, 1024>>>(topi, slotpos, ecnt);
    scatter_kernel<<<NSLOT, 64>>>(SRC, topi, slotpos, DISP);

    // batched expert FFN: z = expert index
    gemm_tf32_kernel<true><<<dim3(FFn / BN, CAPn / BM, En), blk, GEMM_SMEM_BYTES>>>(
        DISP, Dn, (size_t)CAPn * Dn,
        w1,   FFn, (size_t)Dn * FFn,
        b1,   FFn,
        Hb,   FFn, (size_t)CAPn * FFn,
        Dn, ecnt);
    gemm_tf32_kernel<false><<<dim3(Dn / BN, CAPn / BM, En), blk, GEMM_SMEM_BYTES>>>(
        Hb, FFn, (size_t)CAPn * FFn,
        w2, Dn,  (size_t)FFn * Dn,
        b2, Dn,
        Yb, Dn,  (size_t)CAPn * Dn,
        FFn, ecnt);

    combine_ln_kernel<<<Tn / 8, 256>>>(SRC, Yb, topi, TW, slotpos,
                                       ln2g, ln2b, out);
}

// round 7
// speedup vs baseline: 4.2783x; 1.3212x over previous
#include <cuda_runtime.h>
#include <math.h>
#include <stdint.h>

// ---------------------------------------------------------------------------
// Problem constants
// ---------------------------------------------------------------------------
#define Bn    16
#define Cn    1024
#define Dn    512
#define Hn    8
#define HDn   64
#define En    8
#define Ktop  2
#define FFn   2048
#define Tn    (Bn*Cn)        /* 16384 tokens */
#define CAPn  5120
#define NSLOT (Tn*Ktop)      /* 32768 slots  */

// ---------------------------------------------------------------------------
// Scratch (~571 MB)
// ---------------------------------------------------------------------------
static constexpr size_t NPROJ    = (size_t)Tn * Dn;
static constexpr size_t OFF_Q    = 0;
static constexpr size_t OFF_K    = 1 * NPROJ;
static constexpr size_t OFF_V    = 2 * NPROJ;
static constexpr size_t OFF_ATTN = 3 * NPROJ;
static constexpr size_t OFF_PRJ  = OFF_Q;
static constexpr size_t OFF_SRC  = OFF_K;
static constexpr size_t OFF_DISP = OFF_V;
static constexpr size_t NDISP    = (size_t)En * CAPn * Dn;
static constexpr size_t OFF_H    = OFF_DISP + NDISP;
static constexpr size_t NH       = (size_t)En * CAPn * FFn;
static constexpr size_t OFF_Y    = OFF_H + NH;
static constexpr size_t OFF_TOPW = OFF_Y + NDISP;
static constexpr size_t SCRATCH_FLOATS = OFF_TOPW + NSLOT;

__device__ float g_scratch[SCRATCH_FLOATS];
__device__ int   g_iscratch[2 * NSLOT + 8];

// ---------------------------------------------------------------------------
static __device__ __forceinline__ float gelu_fn(float x) {
    float x3 = x * x * x;
    float u  = 0.7978845608028654f * (x + 0.044715f * x3);
    return 0.5f * x * (1.0f + tanhf(u));
}

static __device__ __forceinline__ uint32_t f2tf(float x) {
    uint32_t u;
    asm("cvt.rna.tf32.f32 %0, %1;" : "=r"(u) : "f"(x));
    return u;
}

#define MMA_TF32(acc, a, b0, b1)                                              \
    asm volatile(                                                             \
        "mma.sync.aligned.m16n8k8.row.col.f32.tf32.tf32.f32 "                 \
        "{%0,%1,%2,%3}, {%4,%5,%6,%7}, {%8,%9}, {%0,%1,%2,%3};"               \
        : "+f"(acc[0]), "+f"(acc[1]), "+f"(acc[2]), "+f"(acc[3])              \
        : "r"(a[0]), "r"(a[1]), "r"(a[2]), "r"(a[3]), "r"(b0), "r"(b1))

static __device__ __forceinline__ void cp_async16(uint32_t saddr, const float* g) {
    asm volatile("cp.async.cg.shared.global [%0], [%1], 16;" :: "r"(saddr), "l"(g));
}

// ---------------------------------------------------------------------------
// tf32 tensor-core GEMM, 3-stage cp.async pipeline, z-batched.
//   C[z][M,N] = A[z][M,K] @ B[z][K,N] + bias[z]   (opt GELU)
// 128x128x32 block tile, 128 threads (4 warps 2x2), warp tile 64x64.
// Smem (dynamic, 105KB): 3 stages of A [128][36] fp32 + B [32][136] fp32.
// tf32 cvt (rna) at fragment-load time. mcount[z] early-exit.
// ---------------------------------------------------------------------------
#define BM 128
#define BN 128
#define BKt 32
#define ASTRIDE 36
#define BSTRIDE 136
#define ASTAGE (BM * ASTRIDE)              // 4608 floats
#define BSTAGE (BKt * BSTRIDE)             // 4352 floats
#define GEMM_SMEM_BYTES ((3 * (ASTAGE + BSTAGE)) * 4)   // 107520

template <bool GELU>
__global__ __launch_bounds__(128) void gemm_tf32_kernel(
    const float* __restrict__ A, int lda, size_t aZ,
    const float* __restrict__ Bm, int ldb, size_t bZ,
    const float* __restrict__ bias, int biasZ,
    float* __restrict__ C, int ldc, size_t cZ,
    int Kd, const int* __restrict__ mcount)
{
    const int z = blockIdx.z;
    if (mcount && (int)(blockIdx.y * BM) >= mcount[z]) return;

    extern __shared__ float dsm[];
    float* Asm = dsm;                       // [3][BM][ASTRIDE]
    float* Bsm = dsm + 3 * ASTAGE;          // [3][BKt][BSTRIDE]

    const int tid  = threadIdx.x;
    const int wid  = tid >> 5;
    const int lane = tid & 31;
    const int wm   = (wid & 1) * 64;
    const int wnn  = (wid >> 1) * 64;
    const int g    = lane >> 2;
    const int tg   = lane & 3;

    // staging: A -> 8 segments of 16 rows (4 floats/thread/segment);
    //          B -> 8 segments of 4 rows  (4 floats/thread/segment)
    const int arow = tid >> 3;            // 0..15
    const int acol = (tid & 7) * 4;       // 0..28
    const int brow = tid >> 5;            // 0..3
    const int bcol = (tid & 31) * 4;      // 0..124

    const float* Ag = A + z * aZ + (size_t)(blockIdx.y * BM + arow) * lda + acol;
    const float* Bg = Bm + z * bZ + (size_t)brow * ldb + blockIdx.x * BN + bcol;

    const uint32_t asb = (uint32_t)__cvta_generic_to_shared(Asm) +
                         (arow * ASTRIDE + acol) * 4;
    const uint32_t bsb = (uint32_t)__cvta_generic_to_shared(Bsm) +
                         (brow * BSTRIDE + bcol) * 4;

    const int ntile = Kd / BKt;

#define GEMM_PREFETCH(stage, kt)                                              \
    do {                                                                      \
        const float* ga = Ag + (kt) * BKt;                                    \
        const float* gb = Bg + (size_t)(kt) * BKt * ldb;                      \
        uint32_t sa = asb + (stage) * (ASTAGE * 4);                           \
        uint32_t sb = bsb + (stage) * (BSTAGE * 4);                           \
        _Pragma("unroll")                                                     \
        for (int s = 0; s < 8; s++)                                           \
            cp_async16(sa + s * (16 * ASTRIDE * 4), ga + (size_t)s * 16 * lda);\
        _Pragma("unroll")                                                     \
        for (int s = 0; s < 8; s++)                                           \
            cp_async16(sb + s * (4 * BSTRIDE * 4), gb + (size_t)s * 4 * ldb); \
        asm volatile("cp.async.commit_group;");                               \
    } while (0)

    GEMM_PREFETCH(0, 0);
    if (ntile > 1) GEMM_PREFETCH(1, 1);
    else asm volatile("cp.async.commit_group;");

    float acc[4][8][4];
    #pragma unroll
    for (int i = 0; i < 4; i++)
        #pragma unroll
        for (int j = 0; j < 8; j++) {
            acc[i][j][0] = 0.f; acc[i][j][1] = 0.f;
            acc[i][j][2] = 0.f; acc[i][j][3] = 0.f;
        }

    for (int kt = 0; kt < ntile; kt++) {
        if (kt + 2 < ntile) {
            GEMM_PREFETCH((kt + 2) % 3, kt + 2);
            asm volatile("cp.async.wait_group 2;");
        } else if (kt + 1 < ntile) {
            asm volatile("cp.async.wait_group 1;");
        } else {
            asm volatile("cp.async.wait_group 0;");
        }
        __syncthreads();

        const float* Ab = Asm + (kt % 3) * ASTAGE;
        const float* Bb = Bsm + (kt % 3) * BSTAGE;

        #pragma unroll
        for (int kc = 0; kc < 4; kc++) {
            const int k0 = kc * 8;
            uint32_t afr[4][4];
            #pragma unroll
            for (int i = 0; i < 4; i++) {
                const float* ra = Ab + (wm + i * 16 + g) * ASTRIDE + k0;
                const float* rb = Ab + (wm + i * 16 + g + 8) * ASTRIDE + k0;
                afr[i][0] = f2tf(ra[tg]);
                afr[i][1] = f2tf(rb[tg]);
                afr[i][2] = f2tf(ra[tg + 4]);
                afr[i][3] = f2tf(rb[tg + 4]);
            }
            uint32_t bfr[8][2];
            #pragma unroll
            for (int j = 0; j < 8; j++) {
                int n = wnn + j * 8 + g;
                bfr[j][0] = f2tf(Bb[(k0 + tg) * BSTRIDE + n]);
                bfr[j][1] = f2tf(Bb[(k0 + tg + 4) * BSTRIDE + n]);
            }
            #pragma unroll
            for (int i = 0; i < 4; i++)
                #pragma unroll
                for (int j = 0; j < 8; j++)
                    MMA_TF32(acc[i][j], afr[i], bfr[j][0], bfr[j][1]);
        }
        __syncthreads();
    }
#undef GEMM_PREFETCH

    // epilogue
    const float* bz = bias + (size_t)z * biasZ;
    float* Cz = C + z * cZ;
    #pragma unroll
    for (int j = 0; j < 8; j++) {
        const int col = blockIdx.x * BN + wnn + j * 8 + 2 * tg;
        const float2 bb = *(const float2*)(bz + col);
        #pragma unroll
        for (int i = 0; i < 4; i++) {
            const size_t row0 = (size_t)blockIdx.y * BM + wm + i * 16 + g;
            float2 v0, v1;
            v0.x = acc[i][j][0] + bb.x;
            v0.y = acc[i][j][1] + bb.y;
            v1.x = acc[i][j][2] + bb.x;
            v1.y = acc[i][j][3] + bb.y;
            if (GELU) {
                v0.x = gelu_fn(v0.x); v0.y = gelu_fn(v0.y);
                v1.x = gelu_fn(v1.x); v1.y = gelu_fn(v1.y);
            }
            *(float2*)(Cz + row0 * ldc + col)       = v0;
            *(float2*)(Cz + (row0 + 8) * ldc + col) = v1;
        }
    }
}

// ---------------------------------------------------------------------------
// Flash attention, tf32 tensor cores (verified R5, unchanged).
// ---------------------------------------------------------------------------
__global__ __launch_bounds__(128) void attn_mma_kernel(
    const float* __restrict__ Q, const float* __restrict__ Kb,
    const float* __restrict__ V, const int* __restrict__ mask,
    float* __restrict__ O)
{
    __shared__ uint32_t sK[64][68];
    __shared__ uint32_t sV[64][72];
    __shared__ uint32_t sP[4][16][36];
    __shared__ int      sM[64];

    const int tid  = threadIdx.x;
    const int w    = tid >> 5;
    const int lane = tid & 31;
    const int g    = lane >> 2;
    const int tg   = lane & 3;

    const int bh = blockIdx.y;
    const int b  = bh >> 3, h = bh & 7;
    const int q0 = blockIdx.x << 6;
    const size_t rowbase = (size_t)b * Cn;

    const float* QB = Q  + (rowbase + q0) * Dn + h * HDn;
    const float* KB = Kb + rowbase * Dn + h * HDn;
    const float* VB = V  + rowbase * Dn + h * HDn;
    const int*   MB = mask + b * Cn;

    #pragma unroll
    for (int i = 0; i < 8; i++) {
        int slot = tid + i * 128;
        int r = slot >> 4, c4 = (slot & 15) << 2;
        float4 qv = *(const float4*)(QB + (size_t)r * Dn + c4);
        sK[r][c4 + 0] = f2tf(qv.x * 0.125f);
        sK[r][c4 + 1] = f2tf(qv.y * 0.125f);
        sK[r][c4 + 2] = f2tf(qv.z * 0.125f);
        sK[r][c4 + 3] = f2tf(qv.w * 0.125f);
    }
    __syncthreads();

    const int row0 = w * 16 + g;
    uint32_t qa[8][4];
    #pragma unroll
    for (int ks = 0; ks < 8; ks++) {
        qa[ks][0] = sK[row0][8 * ks + tg];
        qa[ks][1] = sK[row0 + 8][8 * ks + tg];
        qa[ks][2] = sK[row0][8 * ks + tg + 4];
        qa[ks][3] = sK[row0 + 8][8 * ks + tg + 4];
    }
    __syncthreads();

    float o[8][4];
    #pragma unroll
    for (int jn = 0; jn < 8; jn++) {
        o[jn][0] = 0.f; o[jn][1] = 0.f; o[jn][2] = 0.f; o[jn][3] = 0.f;
    }
    float mrun0 = -3.0e38f, mrun1 = -3.0e38f;
    float lrun0 = 0.f, lrun1 = 0.f;

    for (int kt = 0; kt < Cn / 64; kt++) {
        const int k0 = kt * 64;
        #pragma unroll
        for (int i = 0; i < 8; i++) {
            int slot = tid + i * 128;
            int r = slot >> 4, c4 = (slot & 15) << 2;
            float4 kv = *(const float4*)(KB + (size_t)(k0 + r) * Dn + c4);
            float4 vv = *(const float4*)(VB + (size_t)(k0 + r) * Dn + c4);
            sK[r][c4 + 0] = f2tf(kv.x); sK[r][c4 + 1] = f2tf(kv.y);
            sK[r][c4 + 2] = f2tf(kv.z); sK[r][c4 + 3] = f2tf(kv.w);
            sV[r][c4 + 0] = f2tf(vv.x); sV[r][c4 + 1] = f2tf(vv.y);
            sV[r][c4 + 2] = f2tf(vv.z); sV[r][c4 + 3] = f2tf(vv.w);
        }
        if (tid < 64) sM[tid] = MB[k0 + tid];
        __syncthreads();

        #pragma unroll
        for (int kc = 0; kc < 2; kc++) {
            float sacc[4][4];
            #pragma unroll
            for (int j = 0; j < 4; j++) {
                sacc[j][0] = 0.f; sacc[j][1] = 0.f;
                sacc[j][2] = 0.f; sacc[j][3] = 0.f;
            }
            #pragma unroll
            for (int ks = 0; ks < 8; ks++) {
                #pragma unroll
                for (int j = 0; j < 4; j++) {
                    int n = kc * 32 + 8 * j + g;
                    uint32_t b0 = sK[n][8 * ks + tg];
                    uint32_t b1 = sK[n][8 * ks + tg + 4];
                    MMA_TF32(sacc[j], qa[ks], b0, b1);
                }
            }

            #pragma unroll
            for (int j = 0; j < 4; j++) {
                int c = kc * 32 + 8 * j + 2 * tg;
                if (sM[c] == 0)     { sacc[j][0] = -1e10f; sacc[j][2] = -1e10f; }
                if (sM[c + 1] == 0) { sacc[j][1] = -1e10f; sacc[j][3] = -1e10f; }
            }

            float mx0 = -3.0e38f, mx1 = -3.0e38f;
            #pragma unroll
            for (int j = 0; j < 4; j++) {
                mx0 = fmaxf(mx0, fmaxf(sacc[j][0], sacc[j][1]));
                mx1 = fmaxf(mx1, fmaxf(sacc[j][2], sacc[j][3]));
            }
            mx0 = fmaxf(mx0, __shfl_xor_sync(0xffffffffu, mx0, 1));
            mx0 = fmaxf(mx0, __shfl_xor_sync(0xffffffffu, mx0, 2));
            mx1 = fmaxf(mx1, __shfl_xor_sync(0xffffffffu, mx1, 1));
            mx1 = fmaxf(mx1, __shfl_xor_sync(0xffffffffu, mx1, 2));

            float mnew0 = fmaxf(mrun0, mx0);
            float mnew1 = fmaxf(mrun1, mx1);
            float corr0 = __expf(mrun0 - mnew0);
            float corr1 = __expf(mrun1 - mnew1);
            mrun0 = mnew0; mrun1 = mnew1;

            float p[4][4];
            float ls0 = 0.f, ls1 = 0.f;
            #pragma unroll
            for (int j = 0; j < 4; j++) {
                p[j][0] = __expf(sacc[j][0] - mnew0);
                p[j][1] = __expf(sacc[j][1] - mnew0);
                p[j][2] = __expf(sacc[j][2] - mnew1);
                p[j][3] = __expf(sacc[j][3] - mnew1);
                ls0 += p[j][0] + p[j][1];
                ls1 += p[j][2] + p[j][3];
            }
            ls0 += __shfl_xor_sync(0xffffffffu, ls0, 1);
            ls0 += __shfl_xor_sync(0xffffffffu, ls0, 2);
            ls1 += __shfl_xor_sync(0xffffffffu, ls1, 1);
            ls1 += __shfl_xor_sync(0xffffffffu, ls1, 2);
            lrun0 = lrun0 * corr0 + ls0;
            lrun1 = lrun1 * corr1 + ls1;

            #pragma unroll
            for (int jn = 0; jn < 8; jn++) {
                o[jn][0] *= corr0; o[jn][1] *= corr0;
                o[jn][2] *= corr1; o[jn][3] *= corr1;
            }

            #pragma unroll
            for (int j = 0; j < 4; j++) {
                int c = 8 * j + 2 * tg;
                sP[w][g][c]         = f2tf(p[j][0]);
                sP[w][g][c + 1]     = f2tf(p[j][1]);
                sP[w][g + 8][c]     = f2tf(p[j][2]);
                sP[w][g + 8][c + 1] = f2tf(p[j][3]);
            }
            __syncwarp();

            uint32_t pa[4][4];
            #pragma unroll
            for (int ks = 0; ks < 4; ks++) {
                pa[ks][0] = sP[w][g][8 * ks + tg];
                pa[ks][1] = sP[w][g + 8][8 * ks + tg];
                pa[ks][2] = sP[w][g][8 * ks + tg + 4];
                pa[ks][3] = sP[w][g + 8][8 * ks + tg + 4];
            }
            __syncwarp();

            #pragma unroll
            for (int ks = 0; ks < 4; ks++) {
                int kr = kc * 32 + 8 * ks;
                #pragma unroll
                for (int jn = 0; jn < 8; jn++) {
                    uint32_t b0 = sV[kr + tg][8 * jn + g];
                    uint32_t b1 = sV[kr + tg + 4][8 * jn + g];
                    MMA_TF32(o[jn], pa[ks], b0, b1);
                }
            }
        }
        __syncthreads();
    }

    const float inv0 = 1.0f / lrun0;
    const float inv1 = 1.0f / lrun1;
    const size_t grow = rowbase + q0 + row0;
    #pragma unroll
    for (int jn = 0; jn < 8; jn++) {
        int col = h * HDn + 8 * jn + 2 * tg;
        float2 v0, v1;
        v0.x = o[jn][0] * inv0; v0.y = o[jn][1] * inv0;
        v1.x = o[jn][2] * inv1; v1.y = o[jn][3] * inv1;
        *(float2*)(O + grow * Dn + col)       = v0;
        *(float2*)(O + (grow + 8) * Dn + col) = v1;
    }
}

// ---------------------------------------------------------------------------
// Residual add + LayerNorm (unchanged).
// ---------------------------------------------------------------------------
__global__ __launch_bounds__(256) void add_ln_kernel(
    const float* __restrict__ A, const float* __restrict__ R,
    const float* __restrict__ gam, const float* __restrict__ bet,
    float* __restrict__ out)
{
    int w    = (blockIdx.x * 256 + threadIdx.x) >> 5;
    int lane = threadIdx.x & 31;
    const float4* a4 = (const float4*)(A + (size_t)w * Dn);
    const float4* r4 = (const float4*)(R + (size_t)w * Dn);
    float4 v[4];
    float s = 0.0f, s2 = 0.0f;
    #pragma unroll
    for (int i = 0; i < 4; i++) {
        float4 xa = a4[lane + i * 32], xr = r4[lane + i * 32];
        v[i].x = xa.x + xr.x; v[i].y = xa.y + xr.y;
        v[i].z = xa.z + xr.z; v[i].w = xa.w + xr.w;
        s  += v[i].x + v[i].y + v[i].z + v[i].w;
        s2 += v[i].x * v[i].x + v[i].y * v[i].y + v[i].z * v[i].z + v[i].w * v[i].w;
    }
    #pragma unroll
    for (int off = 16; off; off >>= 1) {
        s  += __shfl_xor_sync(0xffffffffu, s,  off);
        s2 += __shfl_xor_sync(0xffffffffu, s2, off);
    }
    float mean = s * (1.0f / Dn);
    float var  = s2 * (1.0f / Dn) - mean * mean;
    float inv  = rsqrtf(var + 1e-5f);
    const float4* g4 = (const float4*)gam;
    const float4* b4 = (const float4*)bet;
    float4* o4 = (float4*)(out + (size_t)w * Dn);
    #pragma unroll
    for (int i = 0; i < 4; i++) {
        float4 g = g4[lane + i * 32], be = b4[lane + i * 32];
        float4 r;
        r.x = (v[i].x - mean) * inv * g.x + be.x;
        r.y = (v[i].y - mean) * inv * g.y + be.y;
        r.z = (v[i].z - mean) * inv * g.z + be.z;
        r.w = (v[i].w - mean) * inv * g.w + be.w;
        o4[lane + i * 32] = r;
    }
}

// ---------------------------------------------------------------------------
// Router (unchanged).
// ---------------------------------------------------------------------------
__global__ __launch_bounds__(256) void router_kernel(
    const float* __restrict__ src, const float* __restrict__ rw,
    int* __restrict__ topi, float* __restrict__ topw)
{
    int w    = (blockIdx.x * 256 + threadIdx.x) >> 5;
    int lane = threadIdx.x & 31;
    const float* xr = src + (size_t)w * Dn;
    float acc[8] = {0, 0, 0, 0, 0, 0, 0, 0};
    for (int d = lane; d < Dn; d += 32) {
        float xv = xr[d];
        const float4* r4 = (const float4*)(rw + d * 8);
        float4 r0 = r4[0], r1 = r4[1];
        acc[0] += xv * r0.x; acc[1] += xv * r0.y; acc[2] += xv * r0.z; acc[3] += xv * r0.w;
        acc[4] += xv * r1.x; acc[5] += xv * r1.y; acc[6] += xv * r1.z; acc[7] += xv * r1.w;
    }
    #pragma unroll
    for (int e = 0; e < 8; e++)
        #pragma unroll
        for (int off = 16; off; off >>= 1)
            acc[e] += __shfl_xor_sync(0xffffffffu, acc[e], off);

    if (lane == 0) {
        float mx = acc[0];
        #pragma unroll
        for (int e = 1; e < 8; e++) mx = fmaxf(mx, acc[e]);
        float pe[8], sum = 0.0f;
        #pragma unroll
        for (int e = 0; e < 8; e++) { pe[e] = __expf(acc[e] - mx); sum += pe[e]; }
        float isum = 1.0f / sum;
        #pragma unroll
        for (int e = 0; e < 8; e++) pe[e] *= isum;
        int i1 = 0; float v1 = pe[0];
        #pragma unroll
        for (int e = 1; e < 8; e++) if (pe[e] > v1) { v1 = pe[e]; i1 = e; }
        int i2 = -1; float v2 = -1.0f;
        #pragma unroll
        for (int e = 0; e < 8; e++) if (e != i1 && pe[e] > v2) { v2 = pe[e]; i2 = e; }
        float wn = 1.0f / (v1 + v2);
        topi[2 * w]     = i1;  topi[2 * w + 1] = i2;
        topw[2 * w]     = v1 * wn;  topw[2 * w + 1] = v2 * wn;
    }
}

// ---------------------------------------------------------------------------
// Deterministic capacity scan (unchanged).
// ---------------------------------------------------------------------------
__global__ __launch_bounds__(1024) void scan_kernel(
    const int* __restrict__ topi, int* __restrict__ slotpos,
    int* __restrict__ ecnt)
{
    __shared__ int wtot[32][8];
    __shared__ int wbase[32][8];
    int tid = threadIdx.x, lane = tid & 31, wid = tid >> 5;
    int base = tid * 32;

    int eid[32];
    #pragma unroll
    for (int i = 0; i < 32; i++) eid[i] = topi[base + i];

    int c[8];
    #pragma unroll
    for (int e = 0; e < 8; e++) {
        int ce = 0;
        #pragma unroll
        for (int i = 0; i < 32; i++) ce += (eid[i] == e);
        c[e] = ce;
    }

    int inc[8], excl[8];
    #pragma unroll
    for (int e = 0; e < 8; e++) {
        int v = c[e];
        for (int off = 1; off < 32; off <<= 1) {
            int n = __shfl_up_sync(0xffffffffu, v, off);
            if (lane >= off) v += n;
        }
        inc[e] = v; excl[e] = v - c[e];
    }
    if (lane == 31) {
        #pragma unroll
        for (int e = 0; e < 8; e++) wtot[wid][e] = inc[e];
    }
    __syncthreads();
    if (wid == 0) {
        #pragma unroll
        for (int e = 0; e < 8; e++) {
            int t = wtot[lane][e];
            int v = t;
            for (int off = 1; off < 32; off <<= 1) {
                int n = __shfl_up_sync(0xffffffffu, v, off);
                if (lane >= off) v += n;
            }
            wbase[lane][e] = v - t;
            if (lane == 31) ecnt[e] = min(v, CAPn);
        }
    }
    __syncthreads();

    int run[8];
    #pragma unroll
    for (int e = 0; e < 8; e++) run[e] = wbase[wid][e] + excl[e];

    #pragma unroll
    for (int i = 0; i < 32; i++) {
        int e = eid[i];
        int p = 0;
        #pragma unroll
        for (int ee = 0; ee < 8; ee++)
            if (e == ee) { p = run[ee]; run[ee] = p + 1; }
        slotpos[base + i] = (p < CAPn) ? p : -1;
    }
}

// ---------------------------------------------------------------------------
// Scatter (unchanged).
// ---------------------------------------------------------------------------
__global__ __launch_bounds__(64) void scatter_kernel(
    const float* __restrict__ src, const int* __restrict__ topi,
    const int* __restrict__ slotpos, float* __restrict__ disp)
{
    int s = blockIdx.x;
    int p = slotpos[s];
    if (p < 0) return;
    int e   = topi[s];
    int tok = s >> 1;
    const float4* in4  = (const float4*)(src + (size_t)tok * Dn);
    float4*       out4 = (float4*)(disp + ((size_t)e * CAPn + p) * Dn);
    int t = threadIdx.x;
    out4[t]      = in4[t];
    out4[t + 64] = in4[t + 64];
}

// ---------------------------------------------------------------------------
// Combine + LN2 (unchanged).
// ---------------------------------------------------------------------------
__global__ __launch_bounds__(256) void combine_ln_kernel(
    const float* __restrict__ src, const float* __restrict__ y,
    const int* __restrict__ topi, const float* __restrict__ topw,
    const int* __restrict__ slotpos,
    const float* __restrict__ gam, const float* __restrict__ bet,
    float* __restrict__ out)
{
    int w    = (blockIdx.x * 256 + threadIdx.x) >> 5;
    int lane = threadIdx.x & 31;
    const float4* s4 = (const float4*)(src + (size_t)w * Dn);
    float4 v[4];
    #pragma unroll
    for (int i = 0; i < 4; i++) v[i] = s4[lane + i * 32];

    #pragma unroll
    for (int kk = 0; kk < 2; kk++) {
        int slot = 2 * w + kk;
        int p = slotpos[slot];
        if (p >= 0) {
            int e = topi[slot];
            float ww = topw[slot];
            const float4* y4 = (const float4*)(y + ((size_t)e * CAPn + p) * Dn);
            #pragma unroll
            for (int i = 0; i < 4; i++) {
                float4 yy = y4[lane + i * 32];
                v[i].x += ww * yy.x; v[i].y += ww * yy.y;
                v[i].z += ww * yy.z; v[i].w += ww * yy.w;
            }
        }
    }

    float s = 0.0f, s2 = 0.0f;
    #pragma unroll
    for (int i = 0; i < 4; i++) {
        s  += v[i].x + v[i].y + v[i].z + v[i].w;
        s2 += v[i].x * v[i].x + v[i].y * v[i].y + v[i].z * v[i].z + v[i].w * v[i].w;
    }
    #pragma unroll
    for (int off = 16; off; off >>= 1) {
        s  += __shfl_xor_sync(0xffffffffu, s,  off);
        s2 += __shfl_xor_sync(0xffffffffu, s2, off);
    }
    float mean = s * (1.0f / Dn);
    float var  = s2 * (1.0f / Dn) - mean * mean;
    float inv  = rsqrtf(var + 1e-5f);
    const float4* g4 = (const float4*)gam;
    const float4* b4 = (const float4*)bet;
    float4* o4 = (float4*)(out + (size_t)w * Dn);
    #pragma unroll
    for (int i = 0; i < 4; i++) {
        float4 g = g4[lane + i * 32], be = b4[lane + i * 32];
        float4 r;
        r.x = (v[i].x - mean) * inv * g.x + be.x;
        r.y = (v[i].y - mean) * inv * g.y + be.y;
        r.z = (v[i].z - mean) * inv * g.z + be.z;
        r.w = (v[i].w - mean) * inv * g.w + be.w;
        o4[lane + i * 32] = r;
    }
}

// ---------------------------------------------------------------------------
// Launch sequence
// ---------------------------------------------------------------------------
extern "C" void kernel_launch(void* const* d_in, const int* in_sizes, int n_in,
                              void* d_out, int out_size)
{
    const float* x    = (const float*)d_in[0];
    const int*   msk  = (const int*)  d_in[1];
    const float* wq   = (const float*)d_in[2];
    const float* bq   = (const float*)d_in[3];
    const float* wk   = (const float*)d_in[4];
    const float* bk   = (const float*)d_in[5];
    const float* wv   = (const float*)d_in[6];
    const float* bv   = (const float*)d_in[7];
    const float* wo   = (const float*)d_in[8];
    const float* bo   = (const float*)d_in[9];
    const float* ln1g = (const float*)d_in[10];
    const float* ln1b = (const float*)d_in[11];
    const float* ln2g = (const float*)d_in[12];
    const float* ln2b = (const float*)d_in[13];
    const float* rw   = (const float*)d_in[14];
    const float* w1   = (const float*)d_in[15];
    const float* b1   = (const float*)d_in[16];
    const float* w2   = (const float*)d_in[17];
    const float* b2   = (const float*)d_in[18];
    float* out = (float*)d_out;

    float* S = nullptr;
    int*   I = nullptr;
    cudaGetSymbolAddress((void**)&S, g_scratch);
    cudaGetSymbolAddress((void**)&I, g_iscratch);

    float* Qb   = S + OFF_Q;
    float* Kbuf = S + OFF_K;
    float* Vb   = S + OFF_V;
    float* ATT  = S + OFF_ATTN;
    float* PRJ  = S + OFF_PRJ;
    float* SRC  = S + OFF_SRC;
    float* DISP = S + OFF_DISP;
    float* Hb   = S + OFF_H;
    float* Yb   = S + OFF_Y;
    float* TW   = S + OFF_TOPW;
    int* topi    = I;
    int* slotpos = I + NSLOT;
    int* ecnt    = I + 2 * NSLOT;

    cudaFuncSetAttribute(gemm_tf32_kernel<false>,
                         cudaFuncAttributeMaxDynamicSharedMemorySize,
                         GEMM_SMEM_BYTES);
    cudaFuncSetAttribute(gemm_tf32_kernel<true>,
                         cudaFuncAttributeMaxDynamicSharedMemorySize,
                         GEMM_SMEM_BYTES);

    dim3 blk(128);
    dim3 gproj(Dn / BN, Tn / BM, 1);

    // --- attention block ---
    gemm_tf32_kernel<false><<<gproj, blk, GEMM_SMEM_BYTES>>>(
        x, Dn, 0, wq, Dn, 0, bq, 0, Qb, Dn, 0, Dn, nullptr);
    gemm_tf32_kernel<false><<<gproj, blk, GEMM_SMEM_BYTES>>>(
        x, Dn, 0, wk, Dn, 0, bk, 0, Kbuf, Dn, 0, Dn, nullptr);
    gemm_tf32_kernel<false><<<gproj, blk, GEMM_SMEM_BYTES>>>(
        x, Dn, 0, wv, Dn, 0, bv, 0, Vb, Dn, 0, Dn, nullptr);
    attn_mma_kernel<<<dim3(Cn / 64, Bn * Hn), 128>>>(Qb, Kbuf, Vb, msk, ATT);
    gemm_tf32_kernel<false><<<gproj, blk, GEMM_SMEM_BYTES>>>(
        ATT, Dn, 0, wo, Dn, 0, bo, 0, PRJ, Dn, 0, Dn, nullptr);
    add_ln_kernel<<<Tn / 8, 256>>>(x, PRJ, ln1g, ln1b, SRC);

    // --- MoE block ---
    router_kernel<<<Tn / 8, 256>>>(SRC, rw, topi, TW);
    scan_kernel<<<1, 1024>>>(topi, slotpos, ecnt);
    scatter_kernel<<<NSLOT, 64>>>(SRC, topi, slotpos, DISP);

    // batched expert FFN: z = expert index
    gemm_tf32_kernel<true><<<dim3(FFn / BN, CAPn / BM, En), blk, GEMM_SMEM_BYTES>>>(
        DISP, Dn, (size_t)CAPn * Dn,
        w1,   FFn, (size_t)Dn * FFn,
        b1,   FFn,
        Hb,   FFn, (size_t)CAPn * FFn,
        Dn, ecnt);
    gemm_tf32_kernel<false><<<dim3(Dn / BN, CAPn / BM, En), blk, GEMM_SMEM_BYTES>>>(
        Hb, FFn, (size_t)CAPn * FFn,
        w2, Dn,  (size_t)FFn * Dn,
        b2, Dn,
        Yb, Dn,  (size_t)CAPn * Dn,
        FFn, ecnt);

    combine_ln_kernel<<<Tn / 8, 256>>>(SRC, Yb, topi, TW, slotpos,
                                       ln2g, ln2b, out);
}